// round 10
// baseline (speedup 1.0000x reference)
#include <cuda_runtime.h>
#include <math.h>

#define RF   1024
#define US   200
#define MGC  60
#define FS   64
#define NS   4
#define NL   10
#define NWIN 1600
#define VSCALE 0.70710678118f
#define NT   1024

// Scratch (device globals: no allocation allowed)
__device__ float g_newA[NWIN];
__device__ float g_newB[NWIN];
__device__ float g_cond[NWIN * MGC];
__device__ float g_prep[RF];

// ---------------- prep kernels ----------------
// (also a launch-count shim so ncu -s 5 lands on the last k_stage)
__global__ void k_copy(const float* __restrict__ noise) {
    int i = blockIdx.x * blockDim.x + threadIdx.x;
    if (i < RF) g_prep[i] = noise[i];
}

__global__ void k_cond(const float* __restrict__ mgc,
                       const float* __restrict__ cond_w,
                       const float* __restrict__ cond_b) {
    int n = blockIdx.x;
    int m = threadIdx.x;
    if (m >= MGC) return;
    int f = n / US, u = n % US;
    int r = u * MGC + m;
    const float* wrow = cond_w + (size_t)r * MGC;
    const float* mrow = mgc + f * MGC;
    float acc = cond_b[r];
#pragma unroll
    for (int k = 0; k < MGC; k++) acc += mrow[k] * wrow[k];
    g_cond[n * MGC + m] = tanhf(acc);
}

// ---------------- per-stage kernel: one CTA = one window ----------------
#define SM_XWIN  0
#define SM_COND  1024
#define SM_CPROJ 1088
#define SM_WBUF  2368
#define SM_BUFA  8512
#define SM_BUFB  41280
#define SM_FLOATS (41280 + 16384)
#define SMEM_BYTES (SM_FLOATS * 4)

__device__ __forceinline__ float sigmoidf_(float v) {
    return 1.0f / (1.0f + expf(-v));
}

__device__ __forceinline__ float gatef_(float aI, float aG, float aR) {
    return (tanhf(aI) * sigmoidf_(aG) + aR) * VSCALE;
}

__global__ __launch_bounds__(NT, 1) void k_stage(
    int s,
    const float* __restrict__ noise,
    const float* __restrict__ gin,    // g_new of previous stage (unused for s==0)
    float* __restrict__ gout,         // g_new of this stage
    const float* __restrict__ conv0_w, const float* __restrict__ convs_w,
    const float* __restrict__ conv_b,
    const float* __restrict__ pre_w, const float* __restrict__ pre_b,
    const float* __restrict__ mean_w, const float* __restrict__ mean_b,
    const float* __restrict__ std_w, const float* __restrict__ std_b,
    const float* __restrict__ ccw, const float* __restrict__ ccb,
    float* __restrict__ out)
{
    extern __shared__ float sm[];
    float* xwin  = sm + SM_XWIN;
    float* condv = sm + SM_COND;
    float* cproj = sm + SM_CPROJ;
    float* wbuf  = sm + SM_WBUF;
    float* bufA  = sm + SM_BUFA;
    float* bufB  = sm + SM_BUFB;
    float* wfull = bufA + 8192;     // 24576 floats: free for l>=3

    const int n   = blockIdx.x;
    const int tid = threadIdx.x;

    // input window: prev_x[n .. n+RF)
    for (int i = tid; i < RF; i += NT) {
        int idx = n + i;
        xwin[i] = (s == 0 || idx < RF) ? noise[idx] : gin[idx - RF];
    }
    if (tid < MGC) condv[tid] = g_cond[n * MGC + tid];
    __syncthreads();

    // per-layer conditioning projections: cproj[l*128 + k*64 + o]
    for (int idx = tid; idx < NL * 2 * FS; idx += NT) {
        int l = idx >> 7;
        int k = (idx >> 6) & 1;
        int o = idx & 63;
        int base = ((s * NL + l) * 2 + k) * FS + o;
        const float* wr = ccw + (size_t)base * MGC;
        float acc = ccb[base];
#pragma unroll
        for (int m = 0; m < MGC; m++) acc += condv[m] * wr[m];
        cproj[idx] = acc;
    }
    for (int i = tid; i < 384; i += NT) wbuf[i] = conv0_w[s * 384 + i];
    __syncthreads();

    // ---- layer 0: C=1, L 1024 -> 512 ----
    {
        const float* b = conv_b + (size_t)(s * NL + 0) * 3 * FS;
        for (int idx = tid; idx < FS * 512; idx += NT) {
            int o = idx >> 9, j = idx & 511;
            float x0 = xwin[2 * j], x1 = xwin[2 * j + 1];
            float iv = wbuf[o * 2]       * x0 + wbuf[o * 2 + 1]       * x1 + b[o]      + cproj[o];
            float gv = wbuf[128 + o * 2] * x0 + wbuf[128 + o * 2 + 1] * x1 + b[64 + o] + cproj[64 + o];
            float rv = wbuf[256 + o * 2] * x0 + wbuf[256 + o * 2 + 1] * x1 + b[128 + o];
            bufA[o * 512 + j] = gatef_(iv, gv, rv);
        }
    }

    // ---- layers 1,2: 16-o weight blocks in wbuf ----
    for (int l = 1; l <= 2; l++) {
        const int Lin  = RF >> l;          // 512, 256
        const int Lout = Lin >> 1;         // 256, 128
        const int To   = Lout >> 2;        // 64, 32
        const int toSh = (l == 1) ? 6 : 5;
        float* src = (l & 1) ? bufA : bufB;
        float* dst = (l & 1) ? bufB : bufA;
        const float* Wg = convs_w + (size_t)(s * 9 + (l - 1)) * 3 * FS * FS * 2;
        const float* b  = conv_b + (size_t)(s * NL + l) * 3 * FS;
        const int rs4 = Lin >> 2;

        for (int ob = 0; ob < FS; ob += 16) {
            __syncthreads();
            for (int i = tid; i < 1536; i += NT) {
                int kk = i >> 9, rest = i & 511;
                ((float4*)wbuf)[i] = ((const float4*)(Wg + kk * (FS * 128) + ob * 128))[rest];
            }
            __syncthreads();
            const float2* w2 = (const float2*)wbuf;   // [k][ol][c]
            const int nit = 16 << toSh;
            for (int item = tid; item < nit; item += NT) {
                const int ol = item >> toSh;
                const int q  = item & (To - 1);
                const int o  = ob + ol;
                float acc[12];
#pragma unroll
                for (int a = 0; a < 12; a++) acc[a] = 0.f;
                const float4* r0 = (const float4*)src;
#pragma unroll 2
                for (int c = 0; c < FS; c++) {
                    const float4* r = r0 + c * rs4;
                    float4 xa = r[q];
                    float4 xb = r[q + To];
#pragma unroll
                    for (int k = 0; k < 3; k++) {
                        float2 wv = w2[((k * 16 + ol) << 6) + c];
                        acc[k*4+0] = fmaf(wv.x, xa.x, acc[k*4+0]); acc[k*4+0] = fmaf(wv.y, xa.y, acc[k*4+0]);
                        acc[k*4+1] = fmaf(wv.x, xa.z, acc[k*4+1]); acc[k*4+1] = fmaf(wv.y, xa.w, acc[k*4+1]);
                        acc[k*4+2] = fmaf(wv.x, xb.x, acc[k*4+2]); acc[k*4+2] = fmaf(wv.y, xb.y, acc[k*4+2]);
                        acc[k*4+3] = fmaf(wv.x, xb.z, acc[k*4+3]); acc[k*4+3] = fmaf(wv.y, xb.w, acc[k*4+3]);
                    }
                }
                float bI = b[o] + cproj[l * 128 + o];
                float bG = b[64 + o] + cproj[l * 128 + 64 + o];
                float bR = b[128 + o];
                float2* drow = (float2*)(dst + o * Lout);
                drow[q]      = make_float2(gatef_(acc[0] + bI, acc[4] + bG, acc[8]  + bR),
                                           gatef_(acc[1] + bI, acc[5] + bG, acc[9]  + bR));
                drow[q + To] = make_float2(gatef_(acc[2] + bI, acc[6] + bG, acc[10] + bR),
                                           gatef_(acc[3] + bI, acc[7] + bG, acc[11] + bR));
            }
        }
        __syncthreads();
    }

    // ---- layers 3..7: full-layer weights in wfull, XOR-swizzled [k][o][c^o] ----
    for (int l = 3; l <= 7; l++) {
        const int Lin  = RF >> l;          // 128..8
        const int Lout = Lin >> 1;         // 64..4
        const int toSh = 7 - l;            // log2(To): 4..0
        const int To   = 1 << toSh;
        float* src = (l & 1) ? bufA : bufB;
        float* dst = (l & 1) ? bufB : bufA;
        const float* Wg = convs_w + (size_t)(s * 9 + (l - 1)) * 3 * FS * FS * 2;
        const float* b  = conv_b + (size_t)(s * NL + l) * 3 * FS;
        const int rs4 = Lin >> 2;

        __syncthreads();
        {
            const float2* src2 = (const float2*)Wg;
            float2* w2 = (float2*)wfull;
            for (int g = tid; g < 12288; g += NT) {
                int o = (g >> 6) & 63;
                int didx = (g & ~63) | ((g ^ o) & 63);
                w2[didx] = src2[g];
            }
        }
        __syncthreads();
        const float2* w2 = (const float2*)wfull;
        const int nit = FS << toSh;
        for (int item = tid; item < nit; item += NT) {
            const int o = item >> toSh;
            const int q = item & (To - 1);
            float acc[12];
#pragma unroll
            for (int a = 0; a < 12; a++) acc[a] = 0.f;
            const float4* r0 = (const float4*)src;
#pragma unroll 2
            for (int c = 0; c < FS; c++) {
                const float4* r = r0 + c * rs4;
                float4 xa = r[q];
                float4 xb = r[q + To];
                int cx = c ^ o;
#pragma unroll
                for (int k = 0; k < 3; k++) {
                    float2 wv = w2[(((k << 6) + o) << 6) + cx];
                    acc[k*4+0] = fmaf(wv.x, xa.x, acc[k*4+0]); acc[k*4+0] = fmaf(wv.y, xa.y, acc[k*4+0]);
                    acc[k*4+1] = fmaf(wv.x, xa.z, acc[k*4+1]); acc[k*4+1] = fmaf(wv.y, xa.w, acc[k*4+1]);
                    acc[k*4+2] = fmaf(wv.x, xb.x, acc[k*4+2]); acc[k*4+2] = fmaf(wv.y, xb.y, acc[k*4+2]);
                    acc[k*4+3] = fmaf(wv.x, xb.z, acc[k*4+3]); acc[k*4+3] = fmaf(wv.y, xb.w, acc[k*4+3]);
                }
            }
            float bI = b[o] + cproj[l * 128 + o];
            float bG = b[64 + o] + cproj[l * 128 + 64 + o];
            float bR = b[128 + o];
            float2* drow = (float2*)(dst + o * Lout);
            drow[q]      = make_float2(gatef_(acc[0] + bI, acc[4] + bG, acc[8]  + bR),
                                       gatef_(acc[1] + bI, acc[5] + bG, acc[9]  + bR));
            drow[q + To] = make_float2(gatef_(acc[2] + bI, acc[6] + bG, acc[10] + bR),
                                       gatef_(acc[3] + bI, acc[7] + bG, acc[11] + bR));
        }
        __syncthreads();
    }

    // ---- layer 8: Lin=4, Lout=2 ----
    {
        const int l = 8;
        float* src = bufB;   // l even: src = bufB
        float* dst = bufA;
        const float* Wg = convs_w + (size_t)(s * 9 + (l - 1)) * 3 * FS * FS * 2;
        const float* b  = conv_b + (size_t)(s * NL + l) * 3 * FS;

        __syncthreads();
        {
            const float2* src2 = (const float2*)Wg;
            float2* w2 = (float2*)wfull;
            for (int g = tid; g < 12288; g += NT) {
                int o = (g >> 6) & 63;
                int didx = (g & ~63) | ((g ^ o) & 63);
                w2[didx] = src2[g];
            }
        }
        __syncthreads();
        if (tid < FS) {
            const int o = tid;
            const float2* w2 = (const float2*)wfull;
            float acc[6];
#pragma unroll
            for (int a = 0; a < 6; a++) acc[a] = 0.f;
#pragma unroll 4
            for (int c = 0; c < FS; c++) {
                float4 xa = *(const float4*)(src + (c << 2));
                int cx = c ^ o;
#pragma unroll
                for (int k = 0; k < 3; k++) {
                    float2 wv = w2[(((k << 6) + o) << 6) + cx];
                    acc[k*2+0] = fmaf(wv.x, xa.x, acc[k*2+0]); acc[k*2+0] = fmaf(wv.y, xa.y, acc[k*2+0]);
                    acc[k*2+1] = fmaf(wv.x, xa.z, acc[k*2+1]); acc[k*2+1] = fmaf(wv.y, xa.w, acc[k*2+1]);
                }
            }
            float bI = b[o] + cproj[l * 128 + o];
            float bG = b[64 + o] + cproj[l * 128 + 64 + o];
            float bR = b[128 + o];
            ((float2*)(dst + o * 2))[0] =
                make_float2(gatef_(acc[0] + bI, acc[2] + bG, acc[4] + bR),
                            gatef_(acc[1] + bI, acc[3] + bG, acc[5] + bR));
        }
        __syncthreads();
    }

    // ---- layer 9: Lin=2, Lout=1 ----
    {
        const int l = 9;
        float* src = bufA;
        float* dst = bufB;
        const float* Wg = convs_w + (size_t)(s * 9 + (l - 1)) * 3 * FS * FS * 2;
        const float* b  = conv_b + (size_t)(s * NL + l) * 3 * FS;

        {
            const float2* src2 = (const float2*)Wg;
            float2* w2 = (float2*)wfull;
            for (int g = tid; g < 12288; g += NT) {
                int o = (g >> 6) & 63;
                int didx = (g & ~63) | ((g ^ o) & 63);
                w2[didx] = src2[g];
            }
        }
        __syncthreads();
        if (tid < FS) {
            const int o = tid;
            const float2* w2 = (const float2*)wfull;
            const float2* sr = (const float2*)src;
            float a0 = 0.f, a1 = 0.f, a2 = 0.f;
#pragma unroll 8
            for (int c = 0; c < FS; c++) {
                float2 xv = sr[c];
                int cx = c ^ o;
                float2 w0 = w2[((0 * FS + o) << 6) + cx];
                float2 w1 = w2[((1 * FS + o) << 6) + cx];
                float2 w3 = w2[((2 * FS + o) << 6) + cx];
                a0 = fmaf(w0.x, xv.x, a0); a0 = fmaf(w0.y, xv.y, a0);
                a1 = fmaf(w1.x, xv.x, a1); a1 = fmaf(w1.y, xv.y, a1);
                a2 = fmaf(w3.x, xv.x, a2); a2 = fmaf(w3.y, xv.y, a2);
            }
            float bI = b[o] + cproj[l * 128 + o];
            float bG = b[64 + o] + cproj[l * 128 + 64 + o];
            float bR = b[128 + o];
            dst[o] = gatef_(a0 + bI, a1 + bG, a2 + bR);
        }
        __syncthreads();
    }

    // ---- head: x (64) -> pre (256) -> mean/logvar, fused chain update ----
    {
        float mpart = 0.f, vpart = 0.f;
        if (tid < 256) {
            const int p = tid;
            const float* pw = pre_w + (size_t)(s * 256 + p) * FS;
            float acc = pre_b[s * 256 + p];
#pragma unroll
            for (int o = 0; o < FS; o++) acc += bufB[o] * pw[o];
            float pre = fmaxf(acc, 0.f);
            mpart = pre * mean_w[s * 256 + p];
            vpart = pre * std_w[s * 256 + p];
        }
        float* red  = wbuf;
        float* red2 = wbuf + 256;
        __syncthreads();
        if (tid < 256) { red[tid] = mpart; red2[tid] = vpart; }
        __syncthreads();
        for (int st = 128; st > 0; st >>= 1) {
            if (tid < st) { red[tid] += red[tid + st]; red2[tid] += red2[tid + st]; }
            __syncthreads();
        }
        if (tid == 0) {
            float mean   = red[0]  + mean_b[s];
            float logvar = red2[0] + std_b[s];
            float eps = (s == 0) ? noise[RF + n] : gin[n];
            float nv = eps * expf(0.5f * logvar) + mean;
            gout[n] = nv;
            if (n >= NWIN - RF)
                out[3 * NWIN + s * RF + (n - (NWIN - RF))] = nv;
            if (s == NS - 1) {
                out[n] = nv;
                out[NWIN + n] = mean;
                out[2 * NWIN + n] = logvar;
            }
        }
    }
}

// ---------------- launcher ----------------
extern "C" void kernel_launch(void* const* d_in, const int* in_sizes, int n_in,
                              void* d_out, int out_size) {
    const float* mgc     = (const float*)d_in[0];
    const float* noise   = (const float*)d_in[1];
    const float* cond_w  = (const float*)d_in[2];
    const float* cond_b  = (const float*)d_in[3];
    const float* conv0_w = (const float*)d_in[4];
    const float* convs_w = (const float*)d_in[5];
    const float* conv_b  = (const float*)d_in[6];
    const float* ccw     = (const float*)d_in[7];
    const float* ccb     = (const float*)d_in[8];
    const float* pre_w   = (const float*)d_in[9];
    const float* pre_b   = (const float*)d_in[10];
    const float* mean_w  = (const float*)d_in[11];
    const float* mean_b  = (const float*)d_in[12];
    const float* std_w   = (const float*)d_in[13];
    const float* std_b   = (const float*)d_in[14];
    float* out = (float*)d_out;

    cudaFuncSetAttribute(k_stage, cudaFuncAttributeMaxDynamicSharedMemorySize, SMEM_BYTES);

    float* nA = nullptr; float* nB = nullptr;
    cudaGetSymbolAddress((void**)&nA, g_newA);
    cudaGetSymbolAddress((void**)&nB, g_newB);

    k_copy<<<(RF + 255) / 256, 256>>>(noise);
    k_cond<<<NWIN, 64>>>(mgc, cond_w, cond_b);

    for (int s = 0; s < NS; s++) {
        const float* gin = (s & 1) ? nA : nB;   // s=0 ignores gin
        float* gout      = (s & 1) ? nB : nA;
        k_stage<<<NWIN, NT, SMEM_BYTES>>>(s, noise, gin, gout,
                                          conv0_w, convs_w, conv_b,
                                          pre_w, pre_b, mean_w, mean_b,
                                          std_w, std_b, ccw, ccb, out);
    }
}

// round 11
// speedup vs baseline: 1.0244x; 1.0244x over previous
#include <cuda_runtime.h>
#include <math.h>

#define RF   1024
#define US   200
#define MGC  60
#define FS   64
#define NS   4
#define NL   10
#define NWIN 1600
#define VSCALE 0.70710678118f
#define NT   512

// Scratch (device globals: no allocation allowed)
__device__ float g_newA[NWIN];
__device__ float g_newB[NWIN];
__device__ float g_cond[NWIN * MGC];
__device__ float g_prep[RF];

// ---------------- prep kernels ----------------
// (launch-count shim so ncu -s 5 lands on the last k_stage)
__global__ void k_copy(const float* __restrict__ noise) {
    int i = blockIdx.x * blockDim.x + threadIdx.x;
    if (i < RF) g_prep[i] = noise[i];
}

__global__ void k_cond(const float* __restrict__ mgc,
                       const float* __restrict__ cond_w,
                       const float* __restrict__ cond_b) {
    int n = blockIdx.x;
    int m = threadIdx.x;
    if (m >= MGC) return;
    int f = n / US, u = n % US;
    int r = u * MGC + m;
    const float* wrow = cond_w + (size_t)r * MGC;
    const float* mrow = mgc + f * MGC;
    float acc = cond_b[r];
#pragma unroll
    for (int k = 0; k < MGC; k++) acc += mrow[k] * wrow[k];
    g_cond[n * MGC + m] = tanhf(acc);
}

// ---------------- per-stage kernel: one CTA = one window ----------------
#define SM_XWIN  0
#define SM_COND  1024
#define SM_CPROJ 1088
#define SM_WBUF  2368
#define SM_BUFA  8512
#define SM_BUFB  41280
#define SM_FLOATS (41280 + 16384)
#define SMEM_BYTES (SM_FLOATS * 4)

__device__ __forceinline__ float sigmoidf_(float v) {
    return 1.0f / (1.0f + expf(-v));
}

__device__ __forceinline__ float gatef_(float aI, float aG, float aR) {
    return (tanhf(aI) * sigmoidf_(aG) + aR) * VSCALE;
}

// 4o x 4j register-tile conv over XOR-swizzled full-layer weights.
// wfull layout: float2 [k][o][c^o]; src rows float4; guard tid < 16<<qsh.
__device__ __forceinline__ void conv_tile4_xor(
    const float* __restrict__ src, float* __restrict__ dst,
    const float* __restrict__ wfull,
    const float* __restrict__ b, const float* __restrict__ cproj,
    int l, int Lin, int qsh, int tid)
{
    const int quads = 1 << qsh;
    const int Lout  = Lin >> 1;
    const int To    = quads;
    if (tid < (16 << qsh)) {
        const int og = tid >> qsh;
        const int q  = tid & (quads - 1);
        const int o0 = og << 2;
        float acc[48];
#pragma unroll
        for (int a = 0; a < 48; a++) acc[a] = 0.f;
        const float4* r0 = (const float4*)src;
        const int rs4 = Lin >> 2;
        const float2* w2 = (const float2*)wfull;
#pragma unroll 2
        for (int c = 0; c < FS; c++) {
            const float4* r = r0 + c * rs4;
            float4 xa = r[q];
            float4 xb = r[q + To];
#pragma unroll
            for (int i = 0; i < 4; i++) {
                const int o = o0 + i;
                const int cx = c ^ o;
#pragma unroll
                for (int k = 0; k < 3; k++) {
                    float2 wv = w2[(((k << 6) + o) << 6) + cx];
                    float* a = acc + (i * 3 + k) * 4;
                    a[0] = fmaf(wv.x, xa.x, a[0]); a[0] = fmaf(wv.y, xa.y, a[0]);
                    a[1] = fmaf(wv.x, xa.z, a[1]); a[1] = fmaf(wv.y, xa.w, a[1]);
                    a[2] = fmaf(wv.x, xb.x, a[2]); a[2] = fmaf(wv.y, xb.y, a[2]);
                    a[3] = fmaf(wv.x, xb.z, a[3]); a[3] = fmaf(wv.y, xb.w, a[3]);
                }
            }
        }
#pragma unroll
        for (int i = 0; i < 4; i++) {
            const int o = o0 + i;
            float bI = b[o] + cproj[l * 128 + o];
            float bG = b[64 + o] + cproj[l * 128 + 64 + o];
            float bR = b[128 + o];
            const float* a = acc + i * 12;
            float2* drow = (float2*)(dst + o * Lout);
            drow[q]      = make_float2(gatef_(a[0] + bI, a[4] + bG, a[8]  + bR),
                                       gatef_(a[1] + bI, a[5] + bG, a[9]  + bR));
            drow[q + To] = make_float2(gatef_(a[2] + bI, a[6] + bG, a[10] + bR),
                                       gatef_(a[3] + bI, a[7] + bG, a[11] + bR));
        }
    }
}

__global__ __launch_bounds__(NT, 1) void k_stage(
    int s,
    const float* __restrict__ noise,
    const float* __restrict__ gin,
    float* __restrict__ gout,
    const float* __restrict__ conv0_w, const float* __restrict__ convs_w,
    const float* __restrict__ conv_b,
    const float* __restrict__ pre_w, const float* __restrict__ pre_b,
    const float* __restrict__ mean_w, const float* __restrict__ mean_b,
    const float* __restrict__ std_w, const float* __restrict__ std_b,
    const float* __restrict__ ccw, const float* __restrict__ ccb,
    float* __restrict__ out)
{
    extern __shared__ float sm[];
    float* xwin  = sm + SM_XWIN;
    float* condv = sm + SM_COND;
    float* cproj = sm + SM_CPROJ;
    float* wbuf  = sm + SM_WBUF;
    float* bufA  = sm + SM_BUFA;
    float* bufB  = sm + SM_BUFB;
    float* wfull = bufA + 8192;     // 24576 floats: free for l>=2

    const int n   = blockIdx.x;
    const int tid = threadIdx.x;

    for (int i = tid; i < RF; i += NT) {
        int idx = n + i;
        xwin[i] = (s == 0 || idx < RF) ? noise[idx] : gin[idx - RF];
    }
    if (tid < MGC) condv[tid] = g_cond[n * MGC + tid];
    __syncthreads();

    // cproj[l*128 + k*64 + o]
    for (int idx = tid; idx < NL * 2 * FS; idx += NT) {
        int l = idx >> 7;
        int k = (idx >> 6) & 1;
        int o = idx & 63;
        int base = ((s * NL + l) * 2 + k) * FS + o;
        const float* wr = ccw + (size_t)base * MGC;
        float acc = ccb[base];
#pragma unroll
        for (int m = 0; m < MGC; m++) acc += condv[m] * wr[m];
        cproj[idx] = acc;
    }
    for (int i = tid; i < 384; i += NT) wbuf[i] = conv0_w[s * 384 + i];
    __syncthreads();

    // ---- layer 0: C=1, L 1024 -> 512 ----
    {
        const float* b = conv_b + (size_t)(s * NL + 0) * 3 * FS;
        for (int idx = tid; idx < FS * 512; idx += NT) {
            int o = idx >> 9, j = idx & 511;
            float x0 = xwin[2 * j], x1 = xwin[2 * j + 1];
            float iv = wbuf[o * 2]       * x0 + wbuf[o * 2 + 1]       * x1 + b[o]      + cproj[o];
            float gv = wbuf[128 + o * 2] * x0 + wbuf[128 + o * 2 + 1] * x1 + b[64 + o] + cproj[64 + o];
            float rv = wbuf[256 + o * 2] * x0 + wbuf[256 + o * 2 + 1] * x1 + b[128 + o];
            bufA[o * 512 + j] = gatef_(iv, gv, rv);
        }
    }

    // ---- layer 1: 4 blocks of 16 o, 4o x 4j tiles ----
    {
        const int Lin = 512, Lout = 256, To = 64;
        const float* src = bufA;
        float* dst = bufB;
        const float* Wg = convs_w + (size_t)(s * 9 + 0) * 3 * FS * FS * 2;
        const float* b  = conv_b + (size_t)(s * NL + 1) * 3 * FS;

        for (int ob = 0; ob < FS; ob += 16) {
            __syncthreads();
            for (int i = tid; i < 1536; i += NT) {
                int kk = i >> 9, rest = i & 511;
                ((float4*)wbuf)[i] = ((const float4*)(Wg + kk * (FS * 128) + ob * 128))[rest];
            }
            __syncthreads();
            if (tid < 256) {
                const int og = tid >> 6;       // 0..3
                const int q  = tid & 63;
                const int ol0 = og << 2;
                float acc[48];
#pragma unroll
                for (int a = 0; a < 48; a++) acc[a] = 0.f;
                const float4* r0 = (const float4*)src;
                const float2* w2 = (const float2*)wbuf;   // [k][ol][c]
#pragma unroll 2
                for (int c = 0; c < FS; c++) {
                    const float4* r = r0 + c * (Lin >> 2);
                    float4 xa = r[q];
                    float4 xb = r[q + To];
#pragma unroll
                    for (int i = 0; i < 4; i++) {
#pragma unroll
                        for (int k = 0; k < 3; k++) {
                            float2 wv = w2[((k * 16 + ol0 + i) << 6) + c];
                            float* a = acc + (i * 3 + k) * 4;
                            a[0] = fmaf(wv.x, xa.x, a[0]); a[0] = fmaf(wv.y, xa.y, a[0]);
                            a[1] = fmaf(wv.x, xa.z, a[1]); a[1] = fmaf(wv.y, xa.w, a[1]);
                            a[2] = fmaf(wv.x, xb.x, a[2]); a[2] = fmaf(wv.y, xb.y, a[2]);
                            a[3] = fmaf(wv.x, xb.z, a[3]); a[3] = fmaf(wv.y, xb.w, a[3]);
                        }
                    }
                }
#pragma unroll
                for (int i = 0; i < 4; i++) {
                    const int o = ob + ol0 + i;
                    float bI = b[o] + cproj[1 * 128 + o];
                    float bG = b[64 + o] + cproj[1 * 128 + 64 + o];
                    float bR = b[128 + o];
                    const float* a = acc + i * 12;
                    float2* drow = (float2*)(dst + o * Lout);
                    drow[q]      = make_float2(gatef_(a[0] + bI, a[4] + bG, a[8]  + bR),
                                               gatef_(a[1] + bI, a[5] + bG, a[9]  + bR));
                    drow[q + To] = make_float2(gatef_(a[2] + bI, a[6] + bG, a[10] + bR),
                                               gatef_(a[3] + bI, a[7] + bG, a[11] + bR));
                }
            }
        }
        __syncthreads();
    }

    // ---- layers 2..7: full-layer weights in wfull (XOR-swizzled), 4o x 4j ----
    for (int l = 2; l <= 7; l++) {
        const int Lin  = RF >> l;          // 256..8
        const int qsh  = 7 - l;            // 5..0
        const float* src = (l & 1) ? bufA : bufB;
        float* dst       = (l & 1) ? bufB : bufA;
        const float* Wg = convs_w + (size_t)(s * 9 + (l - 1)) * 3 * FS * FS * 2;
        const float* b  = conv_b + (size_t)(s * NL + l) * 3 * FS;

        __syncthreads();
        {
            const float2* src2 = (const float2*)Wg;
            float2* w2 = (float2*)wfull;
            for (int g = tid; g < 12288; g += NT) {
                int o = (g >> 6) & 63;
                int didx = (g & ~63) | ((g ^ o) & 63);
                w2[didx] = src2[g];
            }
        }
        __syncthreads();
        conv_tile4_xor(src, dst, wfull, b, cproj, l, Lin, qsh, tid);
        __syncthreads();
    }

    // ---- layer 8: Lin=4, Lout=2 ----
    {
        const int l = 8;
        float* src = bufB;
        float* dst = bufA;
        const float* Wg = convs_w + (size_t)(s * 9 + (l - 1)) * 3 * FS * FS * 2;
        const float* b  = conv_b + (size_t)(s * NL + l) * 3 * FS;

        {
            const float2* src2 = (const float2*)Wg;
            float2* w2 = (float2*)wfull;
            for (int g = tid; g < 12288; g += NT) {
                int o = (g >> 6) & 63;
                int didx = (g & ~63) | ((g ^ o) & 63);
                w2[didx] = src2[g];
            }
        }
        __syncthreads();
        if (tid < FS) {
            const int o = tid;
            const float2* w2 = (const float2*)wfull;
            float acc[6];
#pragma unroll
            for (int a = 0; a < 6; a++) acc[a] = 0.f;
#pragma unroll 4
            for (int c = 0; c < FS; c++) {
                float4 xa = *(const float4*)(src + (c << 2));
                int cx = c ^ o;
#pragma unroll
                for (int k = 0; k < 3; k++) {
                    float2 wv = w2[(((k << 6) + o) << 6) + cx];
                    acc[k*2+0] = fmaf(wv.x, xa.x, acc[k*2+0]); acc[k*2+0] = fmaf(wv.y, xa.y, acc[k*2+0]);
                    acc[k*2+1] = fmaf(wv.x, xa.z, acc[k*2+1]); acc[k*2+1] = fmaf(wv.y, xa.w, acc[k*2+1]);
                }
            }
            float bI = b[o] + cproj[l * 128 + o];
            float bG = b[64 + o] + cproj[l * 128 + 64 + o];
            float bR = b[128 + o];
            ((float2*)(dst + o * 2))[0] =
                make_float2(gatef_(acc[0] + bI, acc[2] + bG, acc[4] + bR),
                            gatef_(acc[1] + bI, acc[3] + bG, acc[5] + bR));
        }
        __syncthreads();
    }

    // ---- layer 9: Lin=2, Lout=1 ----
    {
        const int l = 9;
        float* src = bufA;
        float* dst = bufB;
        const float* Wg = convs_w + (size_t)(s * 9 + (l - 1)) * 3 * FS * FS * 2;
        const float* b  = conv_b + (size_t)(s * NL + l) * 3 * FS;

        {
            const float2* src2 = (const float2*)Wg;
            float2* w2 = (float2*)wfull;
            for (int g = tid; g < 12288; g += NT) {
                int o = (g >> 6) & 63;
                int didx = (g & ~63) | ((g ^ o) & 63);
                w2[didx] = src2[g];
            }
        }
        __syncthreads();
        if (tid < FS) {
            const int o = tid;
            const float2* w2 = (const float2*)wfull;
            const float2* sr = (const float2*)src;
            float a0 = 0.f, a1 = 0.f, a2 = 0.f;
#pragma unroll 8
            for (int c = 0; c < FS; c++) {
                float2 xv = sr[c];
                int cx = c ^ o;
                float2 w0 = w2[((0 * FS + o) << 6) + cx];
                float2 w1 = w2[((1 * FS + o) << 6) + cx];
                float2 w3 = w2[((2 * FS + o) << 6) + cx];
                a0 = fmaf(w0.x, xv.x, a0); a0 = fmaf(w0.y, xv.y, a0);
                a1 = fmaf(w1.x, xv.x, a1); a1 = fmaf(w1.y, xv.y, a1);
                a2 = fmaf(w3.x, xv.x, a2); a2 = fmaf(w3.y, xv.y, a2);
            }
            float bI = b[o] + cproj[l * 128 + o];
            float bG = b[64 + o] + cproj[l * 128 + 64 + o];
            float bR = b[128 + o];
            dst[o] = gatef_(a0 + bI, a1 + bG, a2 + bR);
        }
        __syncthreads();
    }

    // ---- head: x (64) -> pre (256) -> mean/logvar, fused chain update ----
    {
        float mpart = 0.f, vpart = 0.f;
        if (tid < 256) {
            const int p = tid;
            const float* pw = pre_w + (size_t)(s * 256 + p) * FS;
            float acc = pre_b[s * 256 + p];
#pragma unroll
            for (int o = 0; o < FS; o++) acc += bufB[o] * pw[o];
            float pre = fmaxf(acc, 0.f);
            mpart = pre * mean_w[s * 256 + p];
            vpart = pre * std_w[s * 256 + p];
        }
        float* red  = wbuf;
        float* red2 = wbuf + 256;
        __syncthreads();
        if (tid < 256) { red[tid] = mpart; red2[tid] = vpart; }
        __syncthreads();
        for (int st = 128; st > 0; st >>= 1) {
            if (tid < st) { red[tid] += red[tid + st]; red2[tid] += red2[tid + st]; }
            __syncthreads();
        }
        if (tid == 0) {
            float mean   = red[0]  + mean_b[s];
            float logvar = red2[0] + std_b[s];
            float eps = (s == 0) ? noise[RF + n] : gin[n];
            float nv = eps * expf(0.5f * logvar) + mean;
            gout[n] = nv;
            if (n >= NWIN - RF)
                out[3 * NWIN + s * RF + (n - (NWIN - RF))] = nv;
            if (s == NS - 1) {
                out[n] = nv;
                out[NWIN + n] = mean;
                out[2 * NWIN + n] = logvar;
            }
        }
    }
}

// ---------------- launcher ----------------
extern "C" void kernel_launch(void* const* d_in, const int* in_sizes, int n_in,
                              void* d_out, int out_size) {
    const float* mgc     = (const float*)d_in[0];
    const float* noise   = (const float*)d_in[1];
    const float* cond_w  = (const float*)d_in[2];
    const float* cond_b  = (const float*)d_in[3];
    const float* conv0_w = (const float*)d_in[4];
    const float* convs_w = (const float*)d_in[5];
    const float* conv_b  = (const float*)d_in[6];
    const float* ccw     = (const float*)d_in[7];
    const float* ccb     = (const float*)d_in[8];
    const float* pre_w   = (const float*)d_in[9];
    const float* pre_b   = (const float*)d_in[10];
    const float* mean_w  = (const float*)d_in[11];
    const float* mean_b  = (const float*)d_in[12];
    const float* std_w   = (const float*)d_in[13];
    const float* std_b   = (const float*)d_in[14];
    float* out = (float*)d_out;

    cudaFuncSetAttribute(k_stage, cudaFuncAttributeMaxDynamicSharedMemorySize, SMEM_BYTES);

    float* nA = nullptr; float* nB = nullptr;
    cudaGetSymbolAddress((void**)&nA, g_newA);
    cudaGetSymbolAddress((void**)&nB, g_newB);

    k_copy<<<(RF + 255) / 256, 256>>>(noise);
    k_cond<<<NWIN, 64>>>(mgc, cond_w, cond_b);

    for (int s = 0; s < NS; s++) {
        const float* gin = (s & 1) ? nA : nB;   // s=0 ignores gin
        float* gout      = (s & 1) ? nB : nA;
        k_stage<<<NWIN, NT, SMEM_BYTES>>>(s, noise, gin, gout,
                                          conv0_w, convs_w, conv_b,
                                          pre_w, pre_b, mean_w, mean_b,
                                          std_w, std_b, ccw, ccb, out);
    }
}

// round 13
// speedup vs baseline: 1.2706x; 1.2404x over previous
#include <cuda_runtime.h>
#include <math.h>

#define RF   1024
#define US   200
#define MGC  60
#define FS   64
#define NS   4
#define NL   10
#define NWIN 1600
#define VSCALE 0.70710678118f
#define NT   256

// Scratch (device globals: no allocation allowed)
__device__ float g_newA[NWIN];
__device__ float g_newB[NWIN];
__device__ float g_cond[NWIN * MGC];
__device__ float g_cproj[NWIN * NL * 2 * FS];  // [n][l][k][o] -> n*1280 + l*128 + k*64 + o
__device__ float g_l8[NWIN * 2 * FS];          // [n][h][o]

__device__ __forceinline__ float sigmoidf_(float v) { return 1.0f / (1.0f + expf(-v)); }
__device__ __forceinline__ float gatef_(float aI, float aG, float aR) {
    return (tanhf(aI) * sigmoidf_(aG) + aR) * VSCALE;
}

// ---------------- prep kernels ----------------
__global__ void k_cond(const float* __restrict__ mgc,
                       const float* __restrict__ cond_w,
                       const float* __restrict__ cond_b) {
    int n = blockIdx.x;
    int m = threadIdx.x;
    if (m >= MGC) return;
    int f = n / US, u = n % US;
    int r = u * MGC + m;
    const float* wrow = cond_w + (size_t)r * MGC;
    const float* mrow = mgc + f * MGC;
    float acc = cond_b[r];
#pragma unroll
    for (int k = 0; k < MGC; k++) acc += mrow[k] * wrow[k];
    g_cond[n * MGC + m] = tanhf(acc);
}

// weight-stationary cproj precompute: grid (20, 8), 256 thr
// block (ib, nb): idx range [ib*64, ib*64+64), n range [nb*200, nb*200+200)
__global__ void k_cproj(int s, const float* __restrict__ ccw, const float* __restrict__ ccb) {
    __shared__ float wcc[64 * MGC];
    __shared__ float bcc[64];
    const int ib = blockIdx.x, nb = blockIdx.y;
    const int tid = threadIdx.x;
    for (int i = tid; i < 64 * MGC; i += 256) {
        int r = i / MGC, m = i - r * MGC;
        int idx = ib * 64 + r;
        int l = idx >> 7, k = (idx >> 6) & 1, o = idx & 63;
        int base = ((s * NL + l) * 2 + k) * FS + o;
        wcc[i] = ccw[(size_t)base * MGC + m];
        if (m == 0) bcc[r] = ccb[base];
    }
    __syncthreads();
    if (tid < 200) {
        int n = nb * 200 + tid;
        float cv[MGC];
#pragma unroll
        for (int m = 0; m < MGC; m++) cv[m] = g_cond[n * MGC + m];
        for (int r = 0; r < 64; r++) {
            float acc = bcc[r];
            const float* wr = wcc + r * MGC;
#pragma unroll
            for (int m = 0; m < MGC; m++) acc += cv[m] * wr[m];
            g_cproj[n * 1280 + ib * 64 + r] = acc;
        }
    }
}

// ---------------- half-window kernel: CTA = (window n, subtree h) ----------------
// smem (floats): cproj(l0..8) 1152 | wbuf 3072 | bufB 8192 (xwin overlays [0:512)) | bufA 16384
#define SH_CPROJ 0
#define SH_WBUF  1152
#define SH_BUFB  4224
#define SH_BUFA  12416
#define SH_TOT   28800
#define SH_BYTES (SH_TOT * 4)
// wfull = bufA + 4096 (12288 floats), free once l0 output (bufA) has been consumed by l1

__global__ void __launch_bounds__(NT, 2) k_stage_half(
    int s,
    const float* __restrict__ noise,
    const float* __restrict__ gin,
    const float* __restrict__ conv0_w, const float* __restrict__ convs_w,
    const float* __restrict__ conv_b)
{
    extern __shared__ float sm[];
    float* cproj = sm + SH_CPROJ;
    float* wbuf  = sm + SH_WBUF;
    float* bufB  = sm + SH_BUFB;
    float* bufA  = sm + SH_BUFA;
    float* wfull = bufA + 4096;
    float* xwin  = bufB;                 // [0:512), dead after l0

    const int n   = blockIdx.x;
    const int h   = blockIdx.y;
    const int tid = threadIdx.x;

    // inputs
    for (int i = tid; i < 512; i += NT) {
        int idx = n + h * 512 + i;
        xwin[i] = (s == 0 || idx < RF) ? noise[idx] : gin[idx - RF];
    }
    for (int i = tid; i < 1152; i += NT) cproj[i] = g_cproj[n * 1280 + i];
    for (int i = tid; i < 384; i += NT) wbuf[i] = conv0_w[s * 384 + i];
    __syncthreads();

    // ---- l0: C=1, 512 -> 64x256 (bufA) ----
    {
        const float* b = conv_b + (size_t)(s * NL + 0) * 3 * FS;
        for (int idx = tid; idx < FS * 256; idx += NT) {
            int o = idx >> 8, j = idx & 255;
            float x0 = xwin[2 * j], x1 = xwin[2 * j + 1];
            float iv = wbuf[o * 2]       * x0 + wbuf[o * 2 + 1]       * x1 + b[o]      + cproj[o];
            float gv = wbuf[128 + o * 2] * x0 + wbuf[128 + o * 2 + 1] * x1 + b[64 + o] + cproj[64 + o];
            float rv = wbuf[256 + o * 2] * x0 + wbuf[256 + o * 2 + 1] * x1 + b[128 + o];
            bufA[o * 256 + j] = gatef_(iv, gv, rv);
        }
    }

    // ---- l1: bufA(64x256) -> bufB(64x128); 8 blocks of 8 o; 2o x 4j; 128 thr ----
    {
        const float* Wg = convs_w + (size_t)(s * 9 + 0) * 3 * FS * FS * 2;
        const float* b  = conv_b + (size_t)(s * NL + 1) * 3 * FS;
        for (int ob = 0; ob < 8; ob++) {
            __syncthreads();
            for (int g = tid; g < 1536; g += NT) {
                int k = g >> 9, ol = (g >> 6) & 7, c = g & 63;
                ((float2*)wbuf)[g] = ((const float2*)Wg)[(k * 64 + ob * 8 + ol) * 64 + c];
            }
            __syncthreads();
            if (tid < 128) {
                const int og = tid >> 5;      // 0..3
                const int q  = tid & 31;
                const int ol0 = og * 2;
                float acc[24];
#pragma unroll
                for (int a = 0; a < 24; a++) acc[a] = 0.f;
                const float4* r0 = (const float4*)bufA;
                const float2* w2 = (const float2*)wbuf;
#pragma unroll 2
                for (int c = 0; c < 64; c++) {
                    const float4* r = r0 + (c << 6);
                    float4 xa = r[q], xb = r[q + 32];
#pragma unroll
                    for (int i = 0; i < 2; i++) {
#pragma unroll
                        for (int k = 0; k < 3; k++) {
                            float2 wv = w2[((k * 8 + ol0 + i) << 6) + c];
                            float* a = acc + (i * 3 + k) * 4;
                            a[0] = fmaf(wv.x, xa.x, a[0]); a[0] = fmaf(wv.y, xa.y, a[0]);
                            a[1] = fmaf(wv.x, xa.z, a[1]); a[1] = fmaf(wv.y, xa.w, a[1]);
                            a[2] = fmaf(wv.x, xb.x, a[2]); a[2] = fmaf(wv.y, xb.y, a[2]);
                            a[3] = fmaf(wv.x, xb.z, a[3]); a[3] = fmaf(wv.y, xb.w, a[3]);
                        }
                    }
                }
#pragma unroll
                for (int i = 0; i < 2; i++) {
                    const int o = ob * 8 + ol0 + i;
                    float bI = b[o] + cproj[128 + o];
                    float bG = b[64 + o] + cproj[128 + 64 + o];
                    float bR = b[128 + o];
                    const float* a = acc + i * 12;
                    float2* drow = (float2*)(bufB + o * 128);
                    drow[q]      = make_float2(gatef_(a[0] + bI, a[4] + bG, a[8]  + bR),
                                               gatef_(a[1] + bI, a[5] + bG, a[9]  + bR));
                    drow[q + 32] = make_float2(gatef_(a[2] + bI, a[6] + bG, a[10] + bR),
                                               gatef_(a[3] + bI, a[7] + bG, a[11] + bR));
                }
            }
        }
        __syncthreads();
    }

    // ---- l2: bufB(64x128) -> bufA[0:4096] (64x64); wfull 32-o halves; 2o x 4j; 256 thr ----
    {
        const float* Wg = convs_w + (size_t)(s * 9 + 1) * 3 * FS * FS * 2;
        const float* b  = conv_b + (size_t)(s * NL + 2) * 3 * FS;
        for (int ob = 0; ob < 2; ob++) {
            __syncthreads();
            for (int g = tid; g < 6144; g += NT) {
                int k = g >> 11, oL = (g >> 6) & 31, c = g & 63;
                ((float2*)wfull)[(g & ~63) | (c ^ oL)] =
                    ((const float2*)Wg)[(k * 64 + ob * 32 + oL) * 64 + c];
            }
            __syncthreads();
            {
                const int og = tid >> 4;      // 0..15
                const int q  = tid & 15;
                const int oL0 = og * 2;
                float acc[24];
#pragma unroll
                for (int a = 0; a < 24; a++) acc[a] = 0.f;
                const float4* r0 = (const float4*)bufB;
                const float2* w2 = (const float2*)wfull;
#pragma unroll 2
                for (int c = 0; c < 64; c++) {
                    const float4* r = r0 + (c << 5);
                    float4 xa = r[q], xb = r[q + 16];
#pragma unroll
                    for (int i = 0; i < 2; i++) {
                        const int oL = oL0 + i;
                        const int cx = c ^ oL;
#pragma unroll
                        for (int k = 0; k < 3; k++) {
                            float2 wv = w2[((k * 32 + oL) << 6) + cx];
                            float* a = acc + (i * 3 + k) * 4;
                            a[0] = fmaf(wv.x, xa.x, a[0]); a[0] = fmaf(wv.y, xa.y, a[0]);
                            a[1] = fmaf(wv.x, xa.z, a[1]); a[1] = fmaf(wv.y, xa.w, a[1]);
                            a[2] = fmaf(wv.x, xb.x, a[2]); a[2] = fmaf(wv.y, xb.y, a[2]);
                            a[3] = fmaf(wv.x, xb.z, a[3]); a[3] = fmaf(wv.y, xb.w, a[3]);
                        }
                    }
                }
#pragma unroll
                for (int i = 0; i < 2; i++) {
                    const int o = ob * 32 + oL0 + i;
                    float bI = b[o] + cproj[2 * 128 + o];
                    float bG = b[64 + o] + cproj[2 * 128 + 64 + o];
                    float bR = b[128 + o];
                    const float* a = acc + i * 12;
                    float2* drow = (float2*)(bufA + o * 64);
                    drow[q]      = make_float2(gatef_(a[0] + bI, a[4] + bG, a[8]  + bR),
                                               gatef_(a[1] + bI, a[5] + bG, a[9]  + bR));
                    drow[q + 16] = make_float2(gatef_(a[2] + bI, a[6] + bG, a[10] + bR),
                                               gatef_(a[3] + bI, a[7] + bG, a[11] + bR));
                }
            }
        }
        __syncthreads();
    }

    // ---- l3, l4: 1o x 4j; wfull 32-o halves ----
    for (int l = 3; l <= 4; l++) {
        const int LinH  = 512 >> l;         // 64, 32
        const int LoutH = LinH >> 1;        // 32, 16
        const int To    = LoutH >> 2;       // 8, 4
        const int qsh   = (l == 3) ? 3 : 2;
        const float* src = (l & 1) ? bufA : bufB;
        float* dst       = (l & 1) ? bufB : bufA;
        const float* Wg = convs_w + (size_t)(s * 9 + l - 1) * 3 * FS * FS * 2;
        const float* b  = conv_b + (size_t)(s * NL + l) * 3 * FS;
        const int rs4 = LinH >> 2;

        for (int ob = 0; ob < 2; ob++) {
            __syncthreads();
            for (int g = tid; g < 6144; g += NT) {
                int k = g >> 11, oL = (g >> 6) & 31, c = g & 63;
                ((float2*)wfull)[(g & ~63) | (c ^ oL)] =
                    ((const float2*)Wg)[(k * 64 + ob * 32 + oL) * 64 + c];
            }
            __syncthreads();
            if (tid < (32 << qsh)) {
                const int oL = tid >> qsh;
                const int q  = tid & (To - 1);
                float acc[12];
#pragma unroll
                for (int a = 0; a < 12; a++) acc[a] = 0.f;
                const float4* r0 = (const float4*)src;
                const float2* w2 = (const float2*)wfull;
#pragma unroll 2
                for (int c = 0; c < 64; c++) {
                    const float4* r = r0 + c * rs4;
                    float4 xa = r[q], xb = r[q + To];
                    const int cx = c ^ oL;
#pragma unroll
                    for (int k = 0; k < 3; k++) {
                        float2 wv = w2[((k * 32 + oL) << 6) + cx];
                        float* a = acc + k * 4;
                        a[0] = fmaf(wv.x, xa.x, a[0]); a[0] = fmaf(wv.y, xa.y, a[0]);
                        a[1] = fmaf(wv.x, xa.z, a[1]); a[1] = fmaf(wv.y, xa.w, a[1]);
                        a[2] = fmaf(wv.x, xb.x, a[2]); a[2] = fmaf(wv.y, xb.y, a[2]);
                        a[3] = fmaf(wv.x, xb.z, a[3]); a[3] = fmaf(wv.y, xb.w, a[3]);
                    }
                }
                const int o = ob * 32 + oL;
                float bI = b[o] + cproj[l * 128 + o];
                float bG = b[64 + o] + cproj[l * 128 + 64 + o];
                float bR = b[128 + o];
                float2* drow = (float2*)(dst + o * LoutH);
                drow[q]      = make_float2(gatef_(acc[0] + bI, acc[4] + bG, acc[8]  + bR),
                                           gatef_(acc[1] + bI, acc[5] + bG, acc[9]  + bR));
                drow[q + To] = make_float2(gatef_(acc[2] + bI, acc[6] + bG, acc[10] + bR),
                                           gatef_(acc[3] + bI, acc[7] + bG, acc[11] + bR));
            }
        }
        __syncthreads();
    }

    // ---- l5..l8: scalar (o, j); wfull 32-o halves; l8 writes g_l8 ----
    for (int l = 5; l <= 8; l++) {
        const int LinH  = 512 >> l;         // 16, 8, 4, 2
        const int LoutH = LinH >> 1;        // 8, 4, 2, 1
        const int lsh   = 8 - l;            // log2(LoutH)
        const float* src = (l & 1) ? bufA : bufB;
        float* dst       = (l & 1) ? bufB : bufA;
        const float* Wg = convs_w + (size_t)(s * 9 + l - 1) * 3 * FS * FS * 2;
        const float* b  = conv_b + (size_t)(s * NL + l) * 3 * FS;

        for (int ob = 0; ob < 2; ob++) {
            __syncthreads();
            for (int g = tid; g < 6144; g += NT) {
                int k = g >> 11, oL = (g >> 6) & 31, c = g & 63;
                ((float2*)wfull)[(g & ~63) | (c ^ oL)] =
                    ((const float2*)Wg)[(k * 64 + ob * 32 + oL) * 64 + c];
            }
            __syncthreads();
            if (tid < (32 << lsh)) {
                const int oL = tid >> lsh;
                const int j  = tid & (LoutH - 1);
                const float2* w2 = (const float2*)wfull;
                float aI = 0.f, aG = 0.f, aR = 0.f;
#pragma unroll 4
                for (int c = 0; c < 64; c++) {
                    float xe = src[c * LinH + 2 * j];
                    float xo = src[c * LinH + 2 * j + 1];
                    const int cx = c ^ oL;
                    float2 w0 = w2[((0 * 32 + oL) << 6) + cx];
                    float2 w1 = w2[((1 * 32 + oL) << 6) + cx];
                    float2 wr = w2[((2 * 32 + oL) << 6) + cx];
                    aI = fmaf(w0.x, xe, aI); aI = fmaf(w0.y, xo, aI);
                    aG = fmaf(w1.x, xe, aG); aG = fmaf(w1.y, xo, aG);
                    aR = fmaf(wr.x, xe, aR); aR = fmaf(wr.y, xo, aR);
                }
                const int o = ob * 32 + oL;
                float v = gatef_(aI + b[o] + cproj[l * 128 + o],
                                 aG + b[64 + o] + cproj[l * 128 + 64 + o],
                                 aR + b[128 + o]);
                if (l < 8) dst[o * LoutH + j] = v;
                else       g_l8[(n * 2 + h) * FS + o] = v;
            }
        }
        __syncthreads();
    }
}

// ---------------- tail kernel: l9 + head per window ----------------
#define KT_CPROJ 0
#define KT_XIO   128
#define KT_XOUT  256
#define KT_RED   320
#define KT_W     832
#define KT_TOT   (832 + 24576)
#define KT_BYTES (KT_TOT * 4)

__global__ void __launch_bounds__(256) k_tail(
    int s,
    const float* __restrict__ noise,
    const float* __restrict__ gin,
    float* __restrict__ gout,
    const float* __restrict__ convs_w, const float* __restrict__ conv_b,
    const float* __restrict__ pre_w, const float* __restrict__ pre_b,
    const float* __restrict__ mean_w, const float* __restrict__ mean_b,
    const float* __restrict__ std_w, const float* __restrict__ std_b,
    float* __restrict__ out)
{
    extern __shared__ float sm[];
    float* cproj9 = sm + KT_CPROJ;
    float* xio    = sm + KT_XIO;
    float* xout   = sm + KT_XOUT;
    float* red    = sm + KT_RED;
    float* wfull  = sm + KT_W;
    const int n = blockIdx.x, tid = threadIdx.x;

    if (tid < 128) cproj9[tid] = g_cproj[n * 1280 + 9 * 128 + tid];
    if (tid < 64) {
        xio[tid]      = g_l8[(n * 2 + 0) * FS + tid];
        xio[64 + tid] = g_l8[(n * 2 + 1) * FS + tid];
    }
    const float* Wg = convs_w + (size_t)(s * 9 + 8) * 3 * FS * FS * 2;
    for (int g = tid; g < 12288; g += 256) {
        int oL = (g >> 6) & 63, c = g & 63;
        ((float2*)wfull)[(g & ~63) | (c ^ oL)] = ((const float2*)Wg)[g];
    }
    __syncthreads();

    if (tid < 64) {
        const int o = tid;
        const float2* w2 = (const float2*)wfull;
        const float* b = conv_b + (size_t)(s * NL + 9) * 3 * FS;
        float aI = 0.f, aG = 0.f, aR = 0.f;
#pragma unroll 8
        for (int c = 0; c < 64; c++) {
            float xe = xio[c], xo = xio[64 + c];
            const int cx = c ^ o;
            float2 w0 = w2[((0 * 64 + o) << 6) + cx];
            float2 w1 = w2[((1 * 64 + o) << 6) + cx];
            float2 wr = w2[((2 * 64 + o) << 6) + cx];
            aI = fmaf(w0.x, xe, aI); aI = fmaf(w0.y, xo, aI);
            aG = fmaf(w1.x, xe, aG); aG = fmaf(w1.y, xo, aG);
            aR = fmaf(wr.x, xe, aR); aR = fmaf(wr.y, xo, aR);
        }
        xout[o] = gatef_(aI + b[o] + cproj9[o],
                         aG + b[64 + o] + cproj9[64 + o],
                         aR + b[128 + o]);
    }
    __syncthreads();

    // head: pre (256) -> mean/logvar
    {
        const int p = tid;
        const float* pw = pre_w + (size_t)(s * 256 + p) * FS;
        float acc = pre_b[s * 256 + p];
#pragma unroll
        for (int o = 0; o < FS; o++) acc += xout[o] * pw[o];
        float pre = fmaxf(acc, 0.f);
        red[tid]       = pre * mean_w[s * 256 + p];
        red[256 + tid] = pre * std_w[s * 256 + p];
    }
    __syncthreads();
    for (int st = 128; st > 0; st >>= 1) {
        if (tid < st) { red[tid] += red[tid + st]; red[256 + tid] += red[256 + tid + st]; }
        __syncthreads();
    }
    if (tid == 0) {
        float mean   = red[0]   + mean_b[s];
        float logvar = red[256] + std_b[s];
        float eps = (s == 0) ? noise[RF + n] : gin[n];
        float nv = eps * expf(0.5f * logvar) + mean;
        gout[n] = nv;
        if (n >= NWIN - RF) out[3 * NWIN + s * RF + (n - (NWIN - RF))] = nv;
        if (s == NS - 1) {
            out[n] = nv;
            out[NWIN + n] = mean;
            out[2 * NWIN + n] = logvar;
        }
    }
}

// ---------------- launcher ----------------
extern "C" void kernel_launch(void* const* d_in, const int* in_sizes, int n_in,
                              void* d_out, int out_size) {
    const float* mgc     = (const float*)d_in[0];
    const float* noise   = (const float*)d_in[1];
    const float* cond_w  = (const float*)d_in[2];
    const float* cond_b  = (const float*)d_in[3];
    const float* conv0_w = (const float*)d_in[4];
    const float* convs_w = (const float*)d_in[5];
    const float* conv_b  = (const float*)d_in[6];
    const float* ccw     = (const float*)d_in[7];
    const float* ccb     = (const float*)d_in[8];
    const float* pre_w   = (const float*)d_in[9];
    const float* pre_b   = (const float*)d_in[10];
    const float* mean_w  = (const float*)d_in[11];
    const float* mean_b  = (const float*)d_in[12];
    const float* std_w   = (const float*)d_in[13];
    const float* std_b   = (const float*)d_in[14];
    float* out = (float*)d_out;

    cudaFuncSetAttribute(k_stage_half, cudaFuncAttributeMaxDynamicSharedMemorySize, SH_BYTES);
    cudaFuncSetAttribute(k_tail, cudaFuncAttributeMaxDynamicSharedMemorySize, KT_BYTES);

    float* nA = nullptr; float* nB = nullptr;
    cudaGetSymbolAddress((void**)&nA, g_newA);
    cudaGetSymbolAddress((void**)&nB, g_newB);

    k_cond<<<NWIN, 64>>>(mgc, cond_w, cond_b);

    for (int s = 0; s < NS; s++) {
        const float* gin = (s & 1) ? nA : nB;   // s=0 ignores gin
        float* gout      = (s & 1) ? nB : nA;
        k_cproj<<<dim3(20, 8), 256>>>(s, ccw, ccb);
        k_stage_half<<<dim3(NWIN, 2), NT, SH_BYTES>>>(s, noise, gin,
                                                      conv0_w, convs_w, conv_b);
        k_tail<<<NWIN, 256, KT_BYTES>>>(s, noise, gin, gout,
                                        convs_w, conv_b, pre_w, pre_b,
                                        mean_w, mean_b, std_w, std_b, out);
    }
}

// round 15
// speedup vs baseline: 1.4022x; 1.1035x over previous
#include <cuda_runtime.h>
#include <math.h>

#define RF   1024
#define US   200
#define MGC  60
#define FS   64
#define NS   4
#define NL   10
#define NWIN 1600
#define VSCALE 0.70710678118f
#define NT   256
#define GW   8          // windows per k_deep CTA
#define HH   (2*GW)     // halves per k_deep CTA

// Scratch (device globals: no allocation allowed)
__device__ float g_newA[NWIN];
__device__ float g_newB[NWIN];
__device__ float g_cond[NWIN * MGC];
__device__ float g_cproj[NWIN * NL * 2 * FS];  // [n][l][k][o] -> n*1280 + l*128 + k*64 + o
__device__ float g_l4[NWIN * 2 * 1024];        // [n*2+h][c][j] (c:64, j:16)

__device__ __forceinline__ float sigmoidf_(float v) { return 1.0f / (1.0f + expf(-v)); }
__device__ __forceinline__ float gatef_(float aI, float aG, float aR) {
    return (tanhf(aI) * sigmoidf_(aG) + aR) * VSCALE;
}

// ---------------- prep kernels ----------------
__global__ void k_cond(const float* __restrict__ mgc,
                       const float* __restrict__ cond_w,
                       const float* __restrict__ cond_b) {
    int n = blockIdx.x;
    int m = threadIdx.x;
    if (m >= MGC) return;
    int f = n / US, u = n % US;
    int r = u * MGC + m;
    const float* wrow = cond_w + (size_t)r * MGC;
    const float* mrow = mgc + f * MGC;
    float acc = cond_b[r];
#pragma unroll
    for (int k = 0; k < MGC; k++) acc += mrow[k] * wrow[k];
    g_cond[n * MGC + m] = tanhf(acc);
}

// weight-stationary cproj precompute: grid (20, 8), 256 thr
__global__ void k_cproj(int s, const float* __restrict__ ccw, const float* __restrict__ ccb) {
    __shared__ float wcc[64 * MGC];
    __shared__ float bcc[64];
    const int ib = blockIdx.x, nb = blockIdx.y;
    const int tid = threadIdx.x;
    for (int i = tid; i < 64 * MGC; i += 256) {
        int r = i / MGC, m = i - r * MGC;
        int idx = ib * 64 + r;
        int l = idx >> 7, k = (idx >> 6) & 1, o = idx & 63;
        int base = ((s * NL + l) * 2 + k) * FS + o;
        wcc[i] = ccw[(size_t)base * MGC + m];
        if (m == 0) bcc[r] = ccb[base];
    }
    __syncthreads();
    if (tid < 200) {
        int n = nb * 200 + tid;
        float cv[MGC];
#pragma unroll
        for (int m = 0; m < MGC; m++) cv[m] = g_cond[n * MGC + m];
        for (int r = 0; r < 64; r++) {
            float acc = bcc[r];
            const float* wr = wcc + r * MGC;
#pragma unroll
            for (int m = 0; m < MGC; m++) acc += cv[m] * wr[m];
            g_cproj[n * 1280 + ib * 64 + r] = acc;
        }
    }
}

// ---------------- half-window kernel (l0..l4): CTA = (window n, subtree h) ----------------
#define SH_CPROJ 0
#define SH_WBUF  1152
#define SH_BUFB  4224
#define SH_BUFA  12416
#define SH_TOT   28800
#define SH_BYTES (SH_TOT * 4)
// wfull = bufA + 4096 (12288 floats), free once l0 output (bufA) consumed by l1

__global__ void __launch_bounds__(NT, 2) k_stage_half(
    int s,
    const float* __restrict__ noise,
    const float* __restrict__ gin,
    const float* __restrict__ conv0_w, const float* __restrict__ convs_w,
    const float* __restrict__ conv_b)
{
    extern __shared__ float sm[];
    float* cproj = sm + SH_CPROJ;
    float* wbuf  = sm + SH_WBUF;
    float* bufB  = sm + SH_BUFB;
    float* bufA  = sm + SH_BUFA;
    float* wfull = bufA + 4096;
    float* xwin  = bufB;                 // [0:512), dead after l0

    const int n   = blockIdx.x;
    const int h   = blockIdx.y;
    const int tid = threadIdx.x;

    for (int i = tid; i < 512; i += NT) {
        int idx = n + h * 512 + i;
        xwin[i] = (s == 0 || idx < RF) ? noise[idx] : gin[idx - RF];
    }
    for (int i = tid; i < 640; i += NT) cproj[i] = g_cproj[n * 1280 + i];  // l0..l4
    for (int i = tid; i < 384; i += NT) wbuf[i] = conv0_w[s * 384 + i];
    __syncthreads();

    // ---- l0: C=1, 512 -> 64x256 (bufA) ----
    {
        const float* b = conv_b + (size_t)(s * NL + 0) * 3 * FS;
        for (int idx = tid; idx < FS * 256; idx += NT) {
            int o = idx >> 8, j = idx & 255;
            float x0 = xwin[2 * j], x1 = xwin[2 * j + 1];
            float iv = wbuf[o * 2]       * x0 + wbuf[o * 2 + 1]       * x1 + b[o]      + cproj[o];
            float gv = wbuf[128 + o * 2] * x0 + wbuf[128 + o * 2 + 1] * x1 + b[64 + o] + cproj[64 + o];
            float rv = wbuf[256 + o * 2] * x0 + wbuf[256 + o * 2 + 1] * x1 + b[128 + o];
            bufA[o * 256 + j] = gatef_(iv, gv, rv);
        }
    }

    // ---- l1: bufA(64x256) -> bufB(64x128); 8 blocks of 8 o; 2o x 4j; 128 thr ----
    {
        const float* Wg = convs_w + (size_t)(s * 9 + 0) * 3 * FS * FS * 2;
        const float* b  = conv_b + (size_t)(s * NL + 1) * 3 * FS;
        for (int ob = 0; ob < 8; ob++) {
            __syncthreads();
            for (int g = tid; g < 1536; g += NT) {
                int k = g >> 9, ol = (g >> 6) & 7, c = g & 63;
                ((float2*)wbuf)[g] = ((const float2*)Wg)[(k * 64 + ob * 8 + ol) * 64 + c];
            }
            __syncthreads();
            if (tid < 128) {
                const int og = tid >> 5;
                const int q  = tid & 31;
                const int ol0 = og * 2;
                float acc[24];
#pragma unroll
                for (int a = 0; a < 24; a++) acc[a] = 0.f;
                const float4* r0 = (const float4*)bufA;
                const float2* w2 = (const float2*)wbuf;
#pragma unroll 2
                for (int c = 0; c < 64; c++) {
                    const float4* r = r0 + (c << 6);
                    float4 xa = r[q], xb = r[q + 32];
#pragma unroll
                    for (int i = 0; i < 2; i++) {
#pragma unroll
                        for (int k = 0; k < 3; k++) {
                            float2 wv = w2[((k * 8 + ol0 + i) << 6) + c];
                            float* a = acc + (i * 3 + k) * 4;
                            a[0] = fmaf(wv.x, xa.x, a[0]); a[0] = fmaf(wv.y, xa.y, a[0]);
                            a[1] = fmaf(wv.x, xa.z, a[1]); a[1] = fmaf(wv.y, xa.w, a[1]);
                            a[2] = fmaf(wv.x, xb.x, a[2]); a[2] = fmaf(wv.y, xb.y, a[2]);
                            a[3] = fmaf(wv.x, xb.z, a[3]); a[3] = fmaf(wv.y, xb.w, a[3]);
                        }
                    }
                }
#pragma unroll
                for (int i = 0; i < 2; i++) {
                    const int o = ob * 8 + ol0 + i;
                    float bI = b[o] + cproj[128 + o];
                    float bG = b[64 + o] + cproj[128 + 64 + o];
                    float bR = b[128 + o];
                    const float* a = acc + i * 12;
                    float2* drow = (float2*)(bufB + o * 128);
                    drow[q]      = make_float2(gatef_(a[0] + bI, a[4] + bG, a[8]  + bR),
                                               gatef_(a[1] + bI, a[5] + bG, a[9]  + bR));
                    drow[q + 32] = make_float2(gatef_(a[2] + bI, a[6] + bG, a[10] + bR),
                                               gatef_(a[3] + bI, a[7] + bG, a[11] + bR));
                }
            }
        }
        __syncthreads();
    }

    // ---- l2: bufB(64x128) -> bufA[0:4096] (64x64); wfull 32-o halves; 2o x 4j ----
    {
        const float* Wg = convs_w + (size_t)(s * 9 + 1) * 3 * FS * FS * 2;
        const float* b  = conv_b + (size_t)(s * NL + 2) * 3 * FS;
        for (int ob = 0; ob < 2; ob++) {
            __syncthreads();
            for (int g = tid; g < 6144; g += NT) {
                int k = g >> 11, oL = (g >> 6) & 31, c = g & 63;
                ((float2*)wfull)[(g & ~63) | (c ^ oL)] =
                    ((const float2*)Wg)[(k * 64 + ob * 32 + oL) * 64 + c];
            }
            __syncthreads();
            {
                const int og = tid >> 4;
                const int q  = tid & 15;
                const int oL0 = og * 2;
                float acc[24];
#pragma unroll
                for (int a = 0; a < 24; a++) acc[a] = 0.f;
                const float4* r0 = (const float4*)bufB;
                const float2* w2 = (const float2*)wfull;
#pragma unroll 2
                for (int c = 0; c < 64; c++) {
                    const float4* r = r0 + (c << 5);
                    float4 xa = r[q], xb = r[q + 16];
#pragma unroll
                    for (int i = 0; i < 2; i++) {
                        const int oL = oL0 + i;
                        const int cx = c ^ oL;
#pragma unroll
                        for (int k = 0; k < 3; k++) {
                            float2 wv = w2[((k * 32 + oL) << 6) + cx];
                            float* a = acc + (i * 3 + k) * 4;
                            a[0] = fmaf(wv.x, xa.x, a[0]); a[0] = fmaf(wv.y, xa.y, a[0]);
                            a[1] = fmaf(wv.x, xa.z, a[1]); a[1] = fmaf(wv.y, xa.w, a[1]);
                            a[2] = fmaf(wv.x, xb.x, a[2]); a[2] = fmaf(wv.y, xb.y, a[2]);
                            a[3] = fmaf(wv.x, xb.z, a[3]); a[3] = fmaf(wv.y, xb.w, a[3]);
                        }
                    }
                }
#pragma unroll
                for (int i = 0; i < 2; i++) {
                    const int o = ob * 32 + oL0 + i;
                    float bI = b[o] + cproj[2 * 128 + o];
                    float bG = b[64 + o] + cproj[2 * 128 + 64 + o];
                    float bR = b[128 + o];
                    const float* a = acc + i * 12;
                    float2* drow = (float2*)(bufA + o * 64);
                    drow[q]      = make_float2(gatef_(a[0] + bI, a[4] + bG, a[8]  + bR),
                                               gatef_(a[1] + bI, a[5] + bG, a[9]  + bR));
                    drow[q + 16] = make_float2(gatef_(a[2] + bI, a[6] + bG, a[10] + bR),
                                               gatef_(a[3] + bI, a[7] + bG, a[11] + bR));
                }
            }
        }
        __syncthreads();
    }

    // ---- l3 (smem->smem), l4 (smem->global g_l4): 1o x 4j; wfull 32-o halves ----
    for (int l = 3; l <= 4; l++) {
        const int LinH  = 512 >> l;         // 64, 32
        const int LoutH = LinH >> 1;        // 32, 16
        const int To    = LoutH >> 2;       // 8, 4
        const int qsh   = (l == 3) ? 3 : 2;
        const float* src = (l & 1) ? bufA : bufB;
        float* dst       = (l & 1) ? bufB : bufA;
        const float* Wg = convs_w + (size_t)(s * 9 + l - 1) * 3 * FS * FS * 2;
        const float* b  = conv_b + (size_t)(s * NL + l) * 3 * FS;
        const int rs4 = LinH >> 2;

        for (int ob = 0; ob < 2; ob++) {
            __syncthreads();
            for (int g = tid; g < 6144; g += NT) {
                int k = g >> 11, oL = (g >> 6) & 31, c = g & 63;
                ((float2*)wfull)[(g & ~63) | (c ^ oL)] =
                    ((const float2*)Wg)[(k * 64 + ob * 32 + oL) * 64 + c];
            }
            __syncthreads();
            if (tid < (32 << qsh)) {
                const int oL = tid >> qsh;
                const int q  = tid & (To - 1);
                float acc[12];
#pragma unroll
                for (int a = 0; a < 12; a++) acc[a] = 0.f;
                const float4* r0 = (const float4*)src;
                const float2* w2 = (const float2*)wfull;
#pragma unroll 2
                for (int c = 0; c < 64; c++) {
                    const float4* r = r0 + c * rs4;
                    float4 xa = r[q], xb = r[q + To];
                    const int cx = c ^ oL;
#pragma unroll
                    for (int k = 0; k < 3; k++) {
                        float2 wv = w2[((k * 32 + oL) << 6) + cx];
                        float* a = acc + k * 4;
                        a[0] = fmaf(wv.x, xa.x, a[0]); a[0] = fmaf(wv.y, xa.y, a[0]);
                        a[1] = fmaf(wv.x, xa.z, a[1]); a[1] = fmaf(wv.y, xa.w, a[1]);
                        a[2] = fmaf(wv.x, xb.x, a[2]); a[2] = fmaf(wv.y, xb.y, a[2]);
                        a[3] = fmaf(wv.x, xb.z, a[3]); a[3] = fmaf(wv.y, xb.w, a[3]);
                    }
                }
                const int o = ob * 32 + oL;
                float bI = b[o] + cproj[l * 128 + o];
                float bG = b[64 + o] + cproj[l * 128 + 64 + o];
                float bR = b[128 + o];
                float2 y0 = make_float2(gatef_(acc[0] + bI, acc[4] + bG, acc[8]  + bR),
                                        gatef_(acc[1] + bI, acc[5] + bG, acc[9]  + bR));
                float2 y1 = make_float2(gatef_(acc[2] + bI, acc[6] + bG, acc[10] + bR),
                                        gatef_(acc[3] + bI, acc[7] + bG, acc[11] + bR));
                if (l == 3) {
                    float2* drow = (float2*)(dst + o * LoutH);
                    drow[q] = y0; drow[q + To] = y1;
                } else {
                    float2* grow = (float2*)(g_l4 + (size_t)(n * 2 + h) * 1024 + o * 16);
                    grow[q] = y0; grow[q + To] = y1;
                }
            }
        }
        if (l == 3) __syncthreads();
    }
}

// ---------------- deep kernel: l5..l9 + head for GW windows per CTA ----------------
// smem (floats): cprojD 5120 | wreg 24576 | act0 16384 | act1 8192
#define KD_CPROJ 0
#define KD_WREG  5120
#define KD_ACT0  29696
#define KD_ACT1  46080
#define KD_TOT   54272
#define KD_BYTES (KD_TOT * 4)
// act0: [0:16384) l5-in; l6-out reuses [0:4096); l8-out at [4096:5120); pre_w overlays [0:16384) for head
// act1: [0:8192) l5-out; l7-out reuses [0:2048); xout [2048:2560); mws/sws [2560:3072); preM [3072:5120); preV [5120:7168)

__global__ void __launch_bounds__(NT, 1) k_deep(
    int s,
    const float* __restrict__ noise,
    const float* __restrict__ gin,
    float* __restrict__ gout,
    const float* __restrict__ convs_w, const float* __restrict__ conv_b,
    const float* __restrict__ pre_w, const float* __restrict__ pre_b,
    const float* __restrict__ mean_w, const float* __restrict__ mean_b,
    const float* __restrict__ std_w, const float* __restrict__ std_b,
    float* __restrict__ out)
{
    extern __shared__ float sm[];
    float* cprojD = sm + KD_CPROJ;     // [w][l5..l9][k][o]: w*640 + li*128 + k*64 + o
    float* wreg   = sm + KD_WREG;
    float* act0   = sm + KD_ACT0;
    float* act1   = sm + KD_ACT1;

    const int w0  = blockIdx.x * GW;
    const int tid = threadIdx.x;

    // load l4 activations for 16 halves: act0[hh*1024 + c*16 + j]
    {
        const float4* gsrc = (const float4*)(g_l4 + (size_t)(w0 * 2) * 1024);
        float4* dst4 = (float4*)act0;
        for (int i = tid; i < 4096; i += NT) dst4[i] = gsrc[i];
    }
    // cproj l5..l9 for 8 windows
    for (int i = tid; i < GW * 640; i += NT) {
        int w = i / 640, r = i - w * 640;
        cprojD[i] = g_cproj[(w0 + w) * 1280 + 5 * 128 + r];
    }
    __syncthreads();

    // ---- conv layers l5..l8 (per half) ----
#pragma unroll
    for (int l = 5; l <= 8; l++) {
        const int jin  = 512 >> l;          // 16, 8, 4, 2  (per-channel input width)
        const int jout = jin >> 1;          // 8, 4, 2, 1
        const int lsh  = 9 - l;             // log2(jin)
        // in/out base pointers per layer
        const float* src = (l == 5) ? act0 : (l == 6) ? act1 : (l == 7) ? act0 : act1;
        float*       dst = (l == 5) ? act1 : (l == 6) ? act0 : (l == 7) ? act1 : (act0 + 4096);
        const float* Wg = convs_w + (size_t)(s * 9 + l - 1) * 3 * FS * FS * 2;
        const float* b  = conv_b + (size_t)(s * NL + l) * 3 * FS;

        __syncthreads();
        for (int g = tid; g < 12288; g += NT) {
            int oL = (g >> 6) & 63, c = g & 63;
            ((float2*)wreg)[(g & ~63) | (c ^ oL)] = ((const float2*)Wg)[g];
        }
        __syncthreads();

        const int nit = HH * 64 * jout;     // 8192, 4096, 2048, 1024
        const float2* w2 = (const float2*)wreg;
        for (int idx = tid; idx < nit; idx += NT) {
            const int j  = idx & (jout - 1);
            const int o  = (idx >> (lsh - 1)) & 63;
            const int hh = idx >> (lsh + 5);
            const float* srow = src + (hh << (lsh + 6));   // 64*jin floats per half
            float aI = 0.f, aG = 0.f, aR = 0.f;
#pragma unroll 4
            for (int c = 0; c < 64; c++) {
                float xe = srow[(c << lsh) + 2 * j];
                float xo = srow[(c << lsh) + 2 * j + 1];
                const int cx = c ^ o;
                float2 wI = w2[((0 * 64 + o) << 6) + cx];
                float2 wG = w2[((1 * 64 + o) << 6) + cx];
                float2 wR = w2[((2 * 64 + o) << 6) + cx];
                aI = fmaf(wI.x, xe, aI); aI = fmaf(wI.y, xo, aI);
                aG = fmaf(wG.x, xe, aG); aG = fmaf(wG.y, xo, aG);
                aR = fmaf(wR.x, xe, aR); aR = fmaf(wR.y, xo, aR);
            }
            const int w = hh >> 1;
            const float* cp = cprojD + w * 640 + (l - 5) * 128;
            float v = gatef_(aI + b[o] + cp[o],
                             aG + b[64 + o] + cp[64 + o],
                             aR + b[128 + o]);
            // output layout: [hh][o][jout] -> per-half stride 64*jout = 1<<(lsh+5)
            dst[(hh << (lsh + 5)) + (o << (lsh - 1)) + j] = v;
        }
    }
    __syncthreads();

    // ---- l9 (per window): in act0[4096 + hh*64 + c], out xout = act1[2048 + w*64 + o] ----
    {
        const float* Wg = convs_w + (size_t)(s * 9 + 8) * 3 * FS * FS * 2;
        const float* b  = conv_b + (size_t)(s * NL + 9) * 3 * FS;
        __syncthreads();
        for (int g = tid; g < 12288; g += NT) {
            int oL = (g >> 6) & 63, c = g & 63;
            ((float2*)wreg)[(g & ~63) | (c ^ oL)] = ((const float2*)Wg)[g];
        }
        __syncthreads();
        const float2* w2 = (const float2*)wreg;
        for (int idx = tid; idx < GW * 64; idx += NT) {
            const int o = idx & 63;
            const int w = idx >> 6;
            const float* E9 = act0 + 4096 + (2 * w) * 64;
            const float* O9 = act0 + 4096 + (2 * w + 1) * 64;
            float aI = 0.f, aG = 0.f, aR = 0.f;
#pragma unroll 8
            for (int c = 0; c < 64; c++) {
                float xe = E9[c], xo = O9[c];
                const int cx = c ^ o;
                float2 wI = w2[((0 * 64 + o) << 6) + cx];
                float2 wG = w2[((1 * 64 + o) << 6) + cx];
                float2 wR = w2[((2 * 64 + o) << 6) + cx];
                aI = fmaf(wI.x, xe, aI); aI = fmaf(wI.y, xo, aI);
                aG = fmaf(wG.x, xe, aG); aG = fmaf(wG.y, xo, aG);
                aR = fmaf(wR.x, xe, aR); aR = fmaf(wR.y, xo, aR);
            }
            const float* cp = cprojD + w * 640 + 4 * 128;
            act1[2048 + w * 64 + o] = gatef_(aI + b[o] + cp[o],
                                             aG + b[64 + o] + cp[64 + o],
                                             aR + b[128 + o]);
        }
    }
    __syncthreads();

    // ---- head: stage pre_w (XOR-banked) into act0, mean/std vecs into act1 ----
    {
        for (int i = tid; i < 16384; i += NT) {
            int p = i >> 6, o = i & 63;
            act0[p * 64 + (o ^ (p & 63))] = pre_w[(size_t)(s * 256 + p) * 64 + o];
        }
        if (tid < 256) {
            act1[2560 + tid] = mean_w[s * 256 + tid];
            act1[2816 + tid] = std_w[s * 256 + tid];
        }
        __syncthreads();

        float* preM = act1 + 3072;
        float* preV = act1 + 5120;
        for (int idx = tid; idx < GW * 256; idx += NT) {
            const int p = idx & 255;
            const int w = idx >> 8;
            const float* xo = act1 + 2048 + w * 64;
            float acc = pre_b[s * 256 + p];
            const float* pw = act0 + p * 64;
            const int px = p & 63;
#pragma unroll 8
            for (int o = 0; o < 64; o++) acc += xo[o] * pw[o ^ px];
            float pre = fmaxf(acc, 0.f);
            preM[w * 256 + p] = pre * act1[2560 + p];
            preV[w * 256 + p] = pre * act1[2816 + p];
        }
        __syncthreads();
        // parallel tree reduce over p for all 8 windows at once
        for (int stsh = 7; stsh >= 0; stsh--) {
            const int st = 1 << stsh;
            for (int ii = tid; ii < (GW << stsh); ii += NT) {
                const int w = ii >> stsh;
                const int p = ii & (st - 1);
                preM[w * 256 + p] += preM[w * 256 + p + st];
                preV[w * 256 + p] += preV[w * 256 + p + st];
            }
            __syncthreads();
        }
        if (tid < GW) {
            const int w = tid;
            const int n = w0 + w;
            float mean   = preM[w * 256] + mean_b[s];
            float logvar = preV[w * 256] + std_b[s];
            float eps = (s == 0) ? noise[RF + n] : gin[n];
            float nv = eps * expf(0.5f * logvar) + mean;
            gout[n] = nv;
            if (n >= NWIN - RF) out[3 * NWIN + s * RF + (n - (NWIN - RF))] = nv;
            if (s == NS - 1) {
                out[n] = nv;
                out[NWIN + n] = mean;
                out[2 * NWIN + n] = logvar;
            }
        }
    }
}

// ---------------- launcher ----------------
extern "C" void kernel_launch(void* const* d_in, const int* in_sizes, int n_in,
                              void* d_out, int out_size) {
    const float* mgc     = (const float*)d_in[0];
    const float* noise   = (const float*)d_in[1];
    const float* cond_w  = (const float*)d_in[2];
    const float* cond_b  = (const float*)d_in[3];
    const float* conv0_w = (const float*)d_in[4];
    const float* convs_w = (const float*)d_in[5];
    const float* conv_b  = (const float*)d_in[6];
    const float* ccw     = (const float*)d_in[7];
    const float* ccb     = (const float*)d_in[8];
    const float* pre_w   = (const float*)d_in[9];
    const float* pre_b   = (const float*)d_in[10];
    const float* mean_w  = (const float*)d_in[11];
    const float* mean_b  = (const float*)d_in[12];
    const float* std_w   = (const float*)d_in[13];
    const float* std_b   = (const float*)d_in[14];
    float* out = (float*)d_out;

    cudaFuncSetAttribute(k_stage_half, cudaFuncAttributeMaxDynamicSharedMemorySize, SH_BYTES);
    cudaFuncSetAttribute(k_deep, cudaFuncAttributeMaxDynamicSharedMemorySize, KD_BYTES);

    float* nA = nullptr; float* nB = nullptr;
    cudaGetSymbolAddress((void**)&nA, g_newA);
    cudaGetSymbolAddress((void**)&nB, g_newB);

    k_cond<<<NWIN, 64>>>(mgc, cond_w, cond_b);

    for (int s = 0; s < NS; s++) {
        const float* gin = (s & 1) ? nA : nB;   // s=0 ignores gin
        float* gout      = (s & 1) ? nB : nA;
        k_cproj<<<dim3(20, 8), 256>>>(s, ccw, ccb);
        k_stage_half<<<dim3(NWIN, 2), NT, SH_BYTES>>>(s, noise, gin,
                                                      conv0_w, convs_w, conv_b);
        k_deep<<<NWIN / GW, NT, KD_BYTES>>>(s, noise, gin, gout,
                                            convs_w, conv_b, pre_w, pre_b,
                                            mean_w, mean_b, std_w, std_b, out);
    }
}

// round 17
// speedup vs baseline: 1.4735x; 1.0509x over previous
#include <cuda_runtime.h>
#include <math.h>

#define RF   1024
#define US   200
#define MGC  60
#define FS   64
#define NS   4
#define NL   10
#define NWIN 1600
#define VSCALE 0.70710678118f
#define NT   256
#define NTD  512        // k_deep block size
#define GW   8          // windows per k_deep CTA
#define HH   (2*GW)     // halves per k_deep CTA
#define CPJ  (NWIN * 1280)

// Scratch (device globals: no allocation allowed)
__device__ float g_newA[NWIN];
__device__ float g_newB[NWIN];
__device__ float g_cond[NWIN * MGC];
__device__ float g_cproj[NS * CPJ];     // [s][n][l][k][o]
__device__ float g_l4[NWIN * 2 * 1024]; // [n*2+h][c][j] (c:64, j:16)

__device__ __forceinline__ float sigmoidf_(float v) { return 1.0f / (1.0f + expf(-v)); }
__device__ __forceinline__ float gatef_(float aI, float aG, float aR) {
    return (tanhf(aI) * sigmoidf_(aG) + aR) * VSCALE;
}

// ---------------- prep kernels ----------------
__global__ void k_cond(const float* __restrict__ mgc,
                       const float* __restrict__ cond_w,
                       const float* __restrict__ cond_b) {
    int n = blockIdx.x;
    int m = threadIdx.x;
    if (m >= MGC) return;
    int f = n / US, u = n % US;
    int r = u * MGC + m;
    const float* wrow = cond_w + (size_t)r * MGC;
    const float* mrow = mgc + f * MGC;
    float acc = cond_b[r];
#pragma unroll
    for (int k = 0; k < MGC; k++) acc += mrow[k] * wrow[k];
    g_cond[n * MGC + m] = tanhf(acc);
}

// weight-stationary cproj precompute for ALL stages: grid (20, 8, NS), 256 thr
__global__ void k_cproj(const float* __restrict__ ccw, const float* __restrict__ ccb) {
    __shared__ float wcc[64 * MGC];
    __shared__ float bcc[64];
    const int ib = blockIdx.x, nb = blockIdx.y, s = blockIdx.z;
    const int tid = threadIdx.x;
    for (int i = tid; i < 64 * MGC; i += 256) {
        int r = i / MGC, m = i - r * MGC;
        int idx = ib * 64 + r;
        int l = idx >> 7, k = (idx >> 6) & 1, o = idx & 63;
        int base = ((s * NL + l) * 2 + k) * FS + o;
        wcc[i] = ccw[(size_t)base * MGC + m];
        if (m == 0) bcc[r] = ccb[base];
    }
    __syncthreads();
    if (tid < 200) {
        int n = nb * 200 + tid;
        float cv[MGC];
#pragma unroll
        for (int m = 0; m < MGC; m++) cv[m] = g_cond[n * MGC + m];
        for (int r = 0; r < 64; r++) {
            float acc = bcc[r];
            const float* wr = wcc + r * MGC;
#pragma unroll
            for (int m = 0; m < MGC; m++) acc += cv[m] * wr[m];
            g_cproj[(size_t)s * CPJ + n * 1280 + ib * 64 + r] = acc;
        }
    }
}

// ---------------- half-window kernel (l0..l4): CTA = (window n, subtree h) ----------------
#define SH_CPROJ 0
#define SH_WBUF  1152
#define SH_BUFB  4224
#define SH_BUFA  12416
#define SH_TOT   28800
#define SH_BYTES (SH_TOT * 4)
// wfull = bufA + 4096 (12288 floats), free once l0 output (bufA) consumed by l1

__global__ void __launch_bounds__(NT, 2) k_stage_half(
    int s,
    const float* __restrict__ noise,
    const float* __restrict__ gin,
    const float* __restrict__ conv0_w, const float* __restrict__ convs_w,
    const float* __restrict__ conv_b)
{
    extern __shared__ float sm[];
    float* cproj = sm + SH_CPROJ;
    float* wbuf  = sm + SH_WBUF;
    float* bufB  = sm + SH_BUFB;
    float* bufA  = sm + SH_BUFA;
    float* wfull = bufA + 4096;
    float* xwin  = bufB;                 // [0:512), dead after l0

    const int n   = blockIdx.x;
    const int h   = blockIdx.y;
    const int tid = threadIdx.x;

    for (int i = tid; i < 512; i += NT) {
        int idx = n + h * 512 + i;
        xwin[i] = (s == 0 || idx < RF) ? noise[idx] : gin[idx - RF];
    }
    for (int i = tid; i < 640; i += NT)
        cproj[i] = g_cproj[(size_t)s * CPJ + n * 1280 + i];  // l0..l4
    for (int i = tid; i < 384; i += NT) wbuf[i] = conv0_w[s * 384 + i];
    __syncthreads();

    // ---- l0: C=1, 512 -> 64x256 (bufA) ----
    {
        const float* b = conv_b + (size_t)(s * NL + 0) * 3 * FS;
        for (int idx = tid; idx < FS * 256; idx += NT) {
            int o = idx >> 8, j = idx & 255;
            float x0 = xwin[2 * j], x1 = xwin[2 * j + 1];
            float iv = wbuf[o * 2]       * x0 + wbuf[o * 2 + 1]       * x1 + b[o]      + cproj[o];
            float gv = wbuf[128 + o * 2] * x0 + wbuf[128 + o * 2 + 1] * x1 + b[64 + o] + cproj[64 + o];
            float rv = wbuf[256 + o * 2] * x0 + wbuf[256 + o * 2 + 1] * x1 + b[128 + o];
            bufA[o * 256 + j] = gatef_(iv, gv, rv);
        }
    }

    // ---- l1: bufA(64x256) -> bufB(64x128); 8 blocks of 8 o; 2o x 4j; 128 thr ----
    {
        const float* Wg = convs_w + (size_t)(s * 9 + 0) * 3 * FS * FS * 2;
        const float* b  = conv_b + (size_t)(s * NL + 1) * 3 * FS;
        for (int ob = 0; ob < 8; ob++) {
            __syncthreads();
            for (int g = tid; g < 1536; g += NT) {
                int k = g >> 9, ol = (g >> 6) & 7, c = g & 63;
                ((float2*)wbuf)[g] = ((const float2*)Wg)[(k * 64 + ob * 8 + ol) * 64 + c];
            }
            __syncthreads();
            if (tid < 128) {
                const int og = tid >> 5;
                const int q  = tid & 31;
                const int ol0 = og * 2;
                float acc[24];
#pragma unroll
                for (int a = 0; a < 24; a++) acc[a] = 0.f;
                const float4* r0 = (const float4*)bufA;
                const float2* w2 = (const float2*)wbuf;
#pragma unroll 2
                for (int c = 0; c < 64; c++) {
                    const float4* r = r0 + (c << 6);
                    float4 xa = r[q], xb = r[q + 32];
#pragma unroll
                    for (int i = 0; i < 2; i++) {
#pragma unroll
                        for (int k = 0; k < 3; k++) {
                            float2 wv = w2[((k * 8 + ol0 + i) << 6) + c];
                            float* a = acc + (i * 3 + k) * 4;
                            a[0] = fmaf(wv.x, xa.x, a[0]); a[0] = fmaf(wv.y, xa.y, a[0]);
                            a[1] = fmaf(wv.x, xa.z, a[1]); a[1] = fmaf(wv.y, xa.w, a[1]);
                            a[2] = fmaf(wv.x, xb.x, a[2]); a[2] = fmaf(wv.y, xb.y, a[2]);
                            a[3] = fmaf(wv.x, xb.z, a[3]); a[3] = fmaf(wv.y, xb.w, a[3]);
                        }
                    }
                }
#pragma unroll
                for (int i = 0; i < 2; i++) {
                    const int o = ob * 8 + ol0 + i;
                    float bI = b[o] + cproj[128 + o];
                    float bG = b[64 + o] + cproj[128 + 64 + o];
                    float bR = b[128 + o];
                    const float* a = acc + i * 12;
                    float2* drow = (float2*)(bufB + o * 128);
                    drow[q]      = make_float2(gatef_(a[0] + bI, a[4] + bG, a[8]  + bR),
                                               gatef_(a[1] + bI, a[5] + bG, a[9]  + bR));
                    drow[q + 32] = make_float2(gatef_(a[2] + bI, a[6] + bG, a[10] + bR),
                                               gatef_(a[3] + bI, a[7] + bG, a[11] + bR));
                }
            }
        }
        __syncthreads();
    }

    // ---- l2: bufB(64x128) -> bufA[0:4096] (64x64); wfull 32-o halves; 2o x 4j ----
    {
        const float* Wg = convs_w + (size_t)(s * 9 + 1) * 3 * FS * FS * 2;
        const float* b  = conv_b + (size_t)(s * NL + 2) * 3 * FS;
        for (int ob = 0; ob < 2; ob++) {
            __syncthreads();
            for (int g = tid; g < 6144; g += NT) {
                int k = g >> 11, oL = (g >> 6) & 31, c = g & 63;
                ((float2*)wfull)[(g & ~63) | (c ^ oL)] =
                    ((const float2*)Wg)[(k * 64 + ob * 32 + oL) * 64 + c];
            }
            __syncthreads();
            {
                const int og = tid >> 4;
                const int q  = tid & 15;
                const int oL0 = og * 2;
                float acc[24];
#pragma unroll
                for (int a = 0; a < 24; a++) acc[a] = 0.f;
                const float4* r0 = (const float4*)bufB;
                const float2* w2 = (const float2*)wfull;
#pragma unroll 2
                for (int c = 0; c < 64; c++) {
                    const float4* r = r0 + (c << 5);
                    float4 xa = r[q], xb = r[q + 16];
#pragma unroll
                    for (int i = 0; i < 2; i++) {
                        const int oL = oL0 + i;
                        const int cx = c ^ oL;
#pragma unroll
                        for (int k = 0; k < 3; k++) {
                            float2 wv = w2[((k * 32 + oL) << 6) + cx];
                            float* a = acc + (i * 3 + k) * 4;
                            a[0] = fmaf(wv.x, xa.x, a[0]); a[0] = fmaf(wv.y, xa.y, a[0]);
                            a[1] = fmaf(wv.x, xa.z, a[1]); a[1] = fmaf(wv.y, xa.w, a[1]);
                            a[2] = fmaf(wv.x, xb.x, a[2]); a[2] = fmaf(wv.y, xb.y, a[2]);
                            a[3] = fmaf(wv.x, xb.z, a[3]); a[3] = fmaf(wv.y, xb.w, a[3]);
                        }
                    }
                }
#pragma unroll
                for (int i = 0; i < 2; i++) {
                    const int o = ob * 32 + oL0 + i;
                    float bI = b[o] + cproj[2 * 128 + o];
                    float bG = b[64 + o] + cproj[2 * 128 + 64 + o];
                    float bR = b[128 + o];
                    const float* a = acc + i * 12;
                    float2* drow = (float2*)(bufA + o * 64);
                    drow[q]      = make_float2(gatef_(a[0] + bI, a[4] + bG, a[8]  + bR),
                                               gatef_(a[1] + bI, a[5] + bG, a[9]  + bR));
                    drow[q + 16] = make_float2(gatef_(a[2] + bI, a[6] + bG, a[10] + bR),
                                               gatef_(a[3] + bI, a[7] + bG, a[11] + bR));
                }
            }
        }
        __syncthreads();
    }

    // ---- l3 (smem->smem), l4 (smem->global g_l4): 1o x 4j; wfull 32-o halves ----
    for (int l = 3; l <= 4; l++) {
        const int LinH  = 512 >> l;
        const int LoutH = LinH >> 1;
        const int To    = LoutH >> 2;
        const int qsh   = (l == 3) ? 3 : 2;
        const float* src = (l & 1) ? bufA : bufB;
        float* dst       = (l & 1) ? bufB : bufA;
        const float* Wg = convs_w + (size_t)(s * 9 + l - 1) * 3 * FS * FS * 2;
        const float* b  = conv_b + (size_t)(s * NL + l) * 3 * FS;
        const int rs4 = LinH >> 2;

        for (int ob = 0; ob < 2; ob++) {
            __syncthreads();
            for (int g = tid; g < 6144; g += NT) {
                int k = g >> 11, oL = (g >> 6) & 31, c = g & 63;
                ((float2*)wfull)[(g & ~63) | (c ^ oL)] =
                    ((const float2*)Wg)[(k * 64 + ob * 32 + oL) * 64 + c];
            }
            __syncthreads();
            if (tid < (32 << qsh)) {
                const int oL = tid >> qsh;
                const int q  = tid & (To - 1);
                float acc[12];
#pragma unroll
                for (int a = 0; a < 12; a++) acc[a] = 0.f;
                const float4* r0 = (const float4*)src;
                const float2* w2 = (const float2*)wfull;
#pragma unroll 2
                for (int c = 0; c < 64; c++) {
                    const float4* r = r0 + c * rs4;
                    float4 xa = r[q], xb = r[q + To];
                    const int cx = c ^ oL;
#pragma unroll
                    for (int k = 0; k < 3; k++) {
                        float2 wv = w2[((k * 32 + oL) << 6) + cx];
                        float* a = acc + k * 4;
                        a[0] = fmaf(wv.x, xa.x, a[0]); a[0] = fmaf(wv.y, xa.y, a[0]);
                        a[1] = fmaf(wv.x, xa.z, a[1]); a[1] = fmaf(wv.y, xa.w, a[1]);
                        a[2] = fmaf(wv.x, xb.x, a[2]); a[2] = fmaf(wv.y, xb.y, a[2]);
                        a[3] = fmaf(wv.x, xb.z, a[3]); a[3] = fmaf(wv.y, xb.w, a[3]);
                    }
                }
                const int o = ob * 32 + oL;
                float bI = b[o] + cproj[l * 128 + o];
                float bG = b[64 + o] + cproj[l * 128 + 64 + o];
                float bR = b[128 + o];
                float2 y0 = make_float2(gatef_(acc[0] + bI, acc[4] + bG, acc[8]  + bR),
                                        gatef_(acc[1] + bI, acc[5] + bG, acc[9]  + bR));
                float2 y1 = make_float2(gatef_(acc[2] + bI, acc[6] + bG, acc[10] + bR),
                                        gatef_(acc[3] + bI, acc[7] + bG, acc[11] + bR));
                if (l == 3) {
                    float2* drow = (float2*)(dst + o * LoutH);
                    drow[q] = y0; drow[q + To] = y1;
                } else {
                    float2* grow = (float2*)(g_l4 + (size_t)(n * 2 + h) * 1024 + o * 16);
                    grow[q] = y0; grow[q + To] = y1;
                }
            }
        }
        if (l == 3) __syncthreads();
    }
}

// ---------------- deep kernel: l5..l9 + head for GW windows per CTA ----------------
// smem (floats): cprojD 5120 | wreg 24576 | act0 16384 | act1 8192
#define KD_CPROJ 0
#define KD_WREG  5120
#define KD_ACT0  29696
#define KD_ACT1  46080
#define KD_TOT   54272
#define KD_BYTES (KD_TOT * 4)
// act0: [0:16384) l5-in; l6-out reuses [0:4096); l8-out at [4096:5120); pre_w overlays [0:16384) for head
// act1: [0:8192) l5-out; l7-out reuses [0:2048); xout [2048:2560); mws/sws [2560:3072); preM [3072:5120); preV [5120:7168)

__global__ void __launch_bounds__(NTD, 1) k_deep(
    int s,
    const float* __restrict__ noise,
    const float* __restrict__ gin,
    float* __restrict__ gout,
    const float* __restrict__ convs_w, const float* __restrict__ conv_b,
    const float* __restrict__ pre_w, const float* __restrict__ pre_b,
    const float* __restrict__ mean_w, const float* __restrict__ mean_b,
    const float* __restrict__ std_w, const float* __restrict__ std_b,
    float* __restrict__ out)
{
    extern __shared__ float sm[];
    float* cprojD = sm + KD_CPROJ;     // [w][l5..l9][k][o]: w*640 + li*128 + k*64 + o
    float* wreg   = sm + KD_WREG;
    float* act0   = sm + KD_ACT0;
    float* act1   = sm + KD_ACT1;

    const int w0  = blockIdx.x * GW;
    const int tid = threadIdx.x;

    // load l4 activations for 16 halves: act0[hh*1024 + c*16 + j]
    {
        const float4* gsrc = (const float4*)(g_l4 + (size_t)(w0 * 2) * 1024);
        float4* dst4 = (float4*)act0;
        for (int i = tid; i < 4096; i += NTD) dst4[i] = gsrc[i];
    }
    // cproj l5..l9 for 8 windows
    for (int i = tid; i < GW * 640; i += NTD) {
        int w = i / 640, r = i - w * 640;
        cprojD[i] = g_cproj[(size_t)s * CPJ + (w0 + w) * 1280 + 5 * 128 + r];
    }
    __syncthreads();

    // ---- conv layers l5..l8 (per half) ----
#pragma unroll
    for (int l = 5; l <= 8; l++) {
        const int jout = 256 >> l;          // 8, 4, 2, 1
        const int lsh  = 9 - l;             // log2(jin)
        const float* src = (l == 5) ? act0 : (l == 6) ? act1 : (l == 7) ? act0 : act1;
        float*       dst = (l == 5) ? act1 : (l == 6) ? act0 : (l == 7) ? act1 : (act0 + 4096);
        const float* Wg = convs_w + (size_t)(s * 9 + l - 1) * 3 * FS * FS * 2;
        const float* b  = conv_b + (size_t)(s * NL + l) * 3 * FS;

        __syncthreads();
        for (int g = tid; g < 12288; g += NTD) {
            int oL = (g >> 6) & 63, c = g & 63;
            ((float2*)wreg)[(g & ~63) | (c ^ oL)] = ((const float2*)Wg)[g];
        }
        __syncthreads();

        const int nit = HH * 64 * jout;     // 8192, 4096, 2048, 1024
        const float2* w2 = (const float2*)wreg;
        for (int idx = tid; idx < nit; idx += NTD) {
            const int j  = idx & (jout - 1);
            const int o  = (idx >> (lsh - 1)) & 63;
            const int hh = idx >> (lsh + 5);
            const float* srow = src + (hh << (lsh + 6));   // 64*jin floats per half
            float aI = 0.f, aG = 0.f, aR = 0.f;
#pragma unroll 4
            for (int c = 0; c < 64; c++) {
                float xe = srow[(c << lsh) + 2 * j];
                float xo = srow[(c << lsh) + 2 * j + 1];
                const int cx = c ^ o;
                float2 wI = w2[((0 * 64 + o) << 6) + cx];
                float2 wG = w2[((1 * 64 + o) << 6) + cx];
                float2 wR = w2[((2 * 64 + o) << 6) + cx];
                aI = fmaf(wI.x, xe, aI); aI = fmaf(wI.y, xo, aI);
                aG = fmaf(wG.x, xe, aG); aG = fmaf(wG.y, xo, aG);
                aR = fmaf(wR.x, xe, aR); aR = fmaf(wR.y, xo, aR);
            }
            const int w = hh >> 1;
            const float* cp = cprojD + w * 640 + (l - 5) * 128;
            float v = gatef_(aI + b[o] + cp[o],
                             aG + b[64 + o] + cp[64 + o],
                             aR + b[128 + o]);
            // output layout: [hh][o][jout] -> per-half stride 64*jout = 1<<(lsh+5)
            dst[(hh << (lsh + 5)) + (o << (lsh - 1)) + j] = v;
        }
    }
    __syncthreads();

    // ---- l9 (per window): in act0[4096 + hh*64 + c], out xout = act1[2048 + w*64 + o] ----
    {
        const float* Wg = convs_w + (size_t)(s * 9 + 8) * 3 * FS * FS * 2;
        const float* b  = conv_b + (size_t)(s * NL + 9) * 3 * FS;
        __syncthreads();
        for (int g = tid; g < 12288; g += NTD) {
            int oL = (g >> 6) & 63, c = g & 63;
            ((float2*)wreg)[(g & ~63) | (c ^ oL)] = ((const float2*)Wg)[g];
        }
        __syncthreads();
        const float2* w2 = (const float2*)wreg;
        for (int idx = tid; idx < GW * 64; idx += NTD) {
            const int o = idx & 63;
            const int w = idx >> 6;
            const float* E9 = act0 + 4096 + (2 * w) * 64;
            const float* O9 = act0 + 4096 + (2 * w + 1) * 64;
            float aI = 0.f, aG = 0.f, aR = 0.f;
#pragma unroll 8
            for (int c = 0; c < 64; c++) {
                float xe = E9[c], xo = O9[c];
                const int cx = c ^ o;
                float2 wI = w2[((0 * 64 + o) << 6) + cx];
                float2 wG = w2[((1 * 64 + o) << 6) + cx];
                float2 wR = w2[((2 * 64 + o) << 6) + cx];
                aI = fmaf(wI.x, xe, aI); aI = fmaf(wI.y, xo, aI);
                aG = fmaf(wG.x, xe, aG); aG = fmaf(wG.y, xo, aG);
                aR = fmaf(wR.x, xe, aR); aR = fmaf(wR.y, xo, aR);
            }
            const float* cp = cprojD + w * 640 + 4 * 128;
            act1[2048 + w * 64 + o] = gatef_(aI + b[o] + cp[o],
                                             aG + b[64 + o] + cp[64 + o],
                                             aR + b[128 + o]);
        }
    }
    __syncthreads();

    // ---- head: stage pre_w (XOR-banked) into act0, mean/std vecs into act1 ----
    {
        for (int i = tid; i < 16384; i += NTD) {
            int p = i >> 6, o = i & 63;
            act0[p * 64 + (o ^ (p & 63))] = pre_w[(size_t)(s * 256 + p) * 64 + o];
        }
        if (tid < 256) {
            act1[2560 + tid] = mean_w[s * 256 + tid];
            act1[2816 + tid] = std_w[s * 256 + tid];
        }
        __syncthreads();

        float* preM = act1 + 3072;
        float* preV = act1 + 5120;
        for (int idx = tid; idx < GW * 256; idx += NTD) {
            const int p = idx & 255;
            const int w = idx >> 8;
            const float* xo = act1 + 2048 + w * 64;
            float acc = pre_b[s * 256 + p];
            const float* pw = act0 + p * 64;
            const int px = p & 63;
#pragma unroll 8
            for (int o = 0; o < 64; o++) acc += xo[o] * pw[o ^ px];
            float pre = fmaxf(acc, 0.f);
            preM[w * 256 + p] = pre * act1[2560 + p];
            preV[w * 256 + p] = pre * act1[2816 + p];
        }
        __syncthreads();
        // parallel tree reduce over p for all 8 windows at once
        for (int stsh = 7; stsh >= 0; stsh--) {
            const int st = 1 << stsh;
            for (int ii = tid; ii < (GW << stsh); ii += NTD) {
                const int w = ii >> stsh;
                const int p = ii & (st - 1);
                preM[w * 256 + p] += preM[w * 256 + p + st];
                preV[w * 256 + p] += preV[w * 256 + p + st];
            }
            __syncthreads();
        }
        if (tid < GW) {
            const int w = tid;
            const int n = w0 + w;
            float mean   = preM[w * 256] + mean_b[s];
            float logvar = preV[w * 256] + std_b[s];
            float eps = (s == 0) ? noise[RF + n] : gin[n];
            float nv = eps * expf(0.5f * logvar) + mean;
            gout[n] = nv;
            if (n >= NWIN - RF) out[3 * NWIN + s * RF + (n - (NWIN - RF))] = nv;
            if (s == NS - 1) {
                out[n] = nv;
                out[NWIN + n] = mean;
                out[2 * NWIN + n] = logvar;
            }
        }
    }
}

// ---------------- launcher ----------------
extern "C" void kernel_launch(void* const* d_in, const int* in_sizes, int n_in,
                              void* d_out, int out_size) {
    const float* mgc     = (const float*)d_in[0];
    const float* noise   = (const float*)d_in[1];
    const float* cond_w  = (const float*)d_in[2];
    const float* cond_b  = (const float*)d_in[3];
    const float* conv0_w = (const float*)d_in[4];
    const float* convs_w = (const float*)d_in[5];
    const float* conv_b  = (const float*)d_in[6];
    const float* ccw     = (const float*)d_in[7];
    const float* ccb     = (const float*)d_in[8];
    const float* pre_w   = (const float*)d_in[9];
    const float* pre_b   = (const float*)d_in[10];
    const float* mean_w  = (const float*)d_in[11];
    const float* mean_b  = (const float*)d_in[12];
    const float* std_w   = (const float*)d_in[13];
    const float* std_b   = (const float*)d_in[14];
    float* out = (float*)d_out;

    cudaFuncSetAttribute(k_stage_half, cudaFuncAttributeMaxDynamicSharedMemorySize, SH_BYTES);
    cudaFuncSetAttribute(k_deep, cudaFuncAttributeMaxDynamicSharedMemorySize, KD_BYTES);

    float* nA = nullptr; float* nB = nullptr;
    cudaGetSymbolAddress((void**)&nA, g_newA);
    cudaGetSymbolAddress((void**)&nB, g_newB);

    k_cond<<<NWIN, 64>>>(mgc, cond_w, cond_b);
    k_cproj<<<dim3(20, 8, NS), 256>>>(ccw, ccb);   // all stages upfront

    for (int s = 0; s < NS; s++) {
        const float* gin = (s & 1) ? nA : nB;   // s=0 ignores gin
        float* gout      = (s & 1) ? nB : nA;
        k_stage_half<<<dim3(NWIN, 2), NT, SH_BYTES>>>(s, noise, gin,
                                                      conv0_w, convs_w, conv_b);
        k_deep<<<NWIN / GW, NTD, KD_BYTES>>>(s, noise, gin, gout,
                                             convs_w, conv_b, pre_w, pre_b,
                                             mean_w, mean_b, std_w, std_b, out);
    }
}